// round 5
// baseline (speedup 1.0000x reference)
#include <cuda_runtime.h>

#define MTOT (256*256)

// Scratch (static device arrays — no allocation in kernel_launch)
__device__ float g_qkvg[(size_t)MTOT * 512];  // [m][q|k|v|g], m = b*256+s
__device__ float g_attn[(size_t)MTOT * 128];  // gated attention output [m][hc]
__device__ float g_Wt [512 * 128];            // W_qkvg transposed: [k=128][n=512]
__device__ float g_Wot[128 * 128];            // W_o transposed:    [k=128][n=128]

// ---------------------------------------------------------------------------
// helpers: tf32 convert + m16n8k8 tf32 MMA
// ---------------------------------------------------------------------------
__device__ __forceinline__ unsigned f2tf(float x) {
    unsigned u;
    asm("cvt.rna.tf32.f32 %0, %1;" : "=r"(u) : "f"(x));
    return u;
}

__device__ __forceinline__ void mma_tf32(float* d, const unsigned* a, const unsigned* b) {
    asm volatile(
        "mma.sync.aligned.m16n8k8.row.col.f32.tf32.tf32.f32 "
        "{%0,%1,%2,%3}, {%4,%5,%6,%7}, {%8,%9}, {%0,%1,%2,%3};"
        : "+f"(d[0]), "+f"(d[1]), "+f"(d[2]), "+f"(d[3])
        : "r"(a[0]), "r"(a[1]), "r"(a[2]), "r"(a[3]),
          "r"(b[0]), "r"(b[1]));
}

// ---------------------------------------------------------------------------
// K0: transpose the two weight matrices (B tiles staged [k][n]).
// ---------------------------------------------------------------------------
__global__ __launch_bounds__(256) void transpose_w_kernel(
    const float* __restrict__ W, const float* __restrict__ Wo)
{
    int idx = blockIdx.x * 256 + threadIdx.x;
    if (idx < 512 * 128) {
        int k = idx >> 9;
        int n = idx & 511;
        g_Wt[idx] = W[n * 128 + k];
    }
    int idx2 = idx - 512 * 128;
    if (idx2 >= 0 && idx2 < 128 * 128) {
        int k = idx2 >> 7;
        int n = idx2 & 127;
        g_Wot[idx2] = Wo[n * 128 + k];
    }
}

// ---------------------------------------------------------------------------
// K1: QKVG projection with tf32 tensor-core MMA.
// C[m][n] = sum_k X[m][k] * Wt[k][n].  M=65536, N=512, K=128.
// Block tile 128x128, 8 warps (4 m-warps x 2 n-warps), warp tile 32x64.
// A staged [m][k] stride 68 (frag banks (4r+c)%32: conflict-free),
// B staged [k][n] stride 136 (frag banks (8k+n)%32: conflict-free).
// Values converted to tf32 (cvt.rna) at staging time.
// ---------------------------------------------------------------------------
#define A_STRIDE 68
#define B_STRIDE 136

__global__ __launch_bounds__(256) void gemm_qkvg_tc_kernel(const float* __restrict__ X)
{
    extern __shared__ unsigned shm[];
    unsigned* Xs = shm;                  // [128][A_STRIDE]
    unsigned* Ws = shm + 128 * A_STRIDE; // [64][B_STRIDE]

    const int tid  = threadIdx.x;
    const int lane = tid & 31;
    const int w    = tid >> 5;         // 0..7
    const int g    = lane >> 2;        // 0..7
    const int tig  = lane & 3;         // 0..3
    const int mw   = (w & 3) * 32;     // warp m offset in tile
    const int nw   = (w >> 2) * 64;    // warp n offset in tile

    const int m0 = blockIdx.x * 128;
    const int n0 = blockIdx.y * 128;

    float acc[2][8][4];
    #pragma unroll
    for (int i = 0; i < 2; i++)
        #pragma unroll
        for (int j = 0; j < 8; j++)
            #pragma unroll
            for (int c = 0; c < 4; c++) acc[i][j][c] = 0.f;

    for (int kc = 0; kc < 128; kc += 64) {
        // stage A: 128 rows x 64 cols
        for (int l = tid; l < 2048; l += 256) {
            int r = l >> 4, c4 = (l & 15) << 2;
            float4 v = *(const float4*)&X[(size_t)(m0 + r) * 128 + kc + c4];
            unsigned* d = &Xs[r * A_STRIDE + c4];
            d[0] = f2tf(v.x); d[1] = f2tf(v.y); d[2] = f2tf(v.z); d[3] = f2tf(v.w);
        }
        // stage B: 64 rows(k) x 128 cols(n)
        for (int l = tid; l < 2048; l += 256) {
            int r = l >> 5, c4 = (l & 31) << 2;
            float4 v = *(const float4*)&g_Wt[(size_t)(kc + r) * 512 + n0 + c4];
            unsigned* d = &Ws[r * B_STRIDE + c4];
            d[0] = f2tf(v.x); d[1] = f2tf(v.y); d[2] = f2tf(v.z); d[3] = f2tf(v.w);
        }
        __syncthreads();

        #pragma unroll
        for (int ks = 0; ks < 64; ks += 8) {
            unsigned a[2][4], b[8][2];
            #pragma unroll
            for (int fm = 0; fm < 2; fm++) {
                int r = mw + fm * 16 + g;
                a[fm][0] = Xs[r * A_STRIDE + ks + tig];
                a[fm][1] = Xs[(r + 8) * A_STRIDE + ks + tig];
                a[fm][2] = Xs[r * A_STRIDE + ks + tig + 4];
                a[fm][3] = Xs[(r + 8) * A_STRIDE + ks + tig + 4];
            }
            #pragma unroll
            for (int fn = 0; fn < 8; fn++) {
                int n = nw + fn * 8 + g;
                b[fn][0] = Ws[(ks + tig) * B_STRIDE + n];
                b[fn][1] = Ws[(ks + tig + 4) * B_STRIDE + n];
            }
            #pragma unroll
            for (int fm = 0; fm < 2; fm++)
                #pragma unroll
                for (int fn = 0; fn < 8; fn++)
                    mma_tf32(acc[fm][fn], a[fm], b[fn]);
        }
        __syncthreads();
    }

    // epilogue: write to g_qkvg
    #pragma unroll
    for (int fm = 0; fm < 2; fm++) {
        int row = m0 + mw + fm * 16 + g;
        #pragma unroll
        for (int fn = 0; fn < 8; fn++) {
            int col = n0 + nw + fn * 8 + 2 * tig;
            float2 lo = { acc[fm][fn][0], acc[fm][fn][1] };
            float2 hi = { acc[fm][fn][2], acc[fm][fn][3] };
            *(float2*)&g_qkvg[(size_t)row * 512 + col] = lo;
            *(float2*)&g_qkvg[(size_t)(row + 8) * 512 + col] = hi;
        }
    }
}

// ---------------------------------------------------------------------------
// K2: fused attention per (h, b).  128 threads, 2 query rows per thread.
// Branch-free softmax (no max subtraction; masked -> exp(-1e9)=0 exactly).
// ---------------------------------------------------------------------------
__global__ __launch_bounds__(128) void attn_kernel(
    const float* __restrict__ mask, const float* __restrict__ bias,
    const float* __restrict__ gbias)
{
    extern __shared__ float sh[];
    float* Ks = sh;               // 256 rows, stride 36
    float* Vs = sh + 256 * 36;

    const int h = blockIdx.x;
    const int b = blockIdx.y;
    const int t = threadIdx.x;    // 0..127

    #pragma unroll
    for (int rr = 0; rr < 2; rr++) {
        int q = t + rr * 128;
        const float4* sk = (const float4*)&g_qkvg[(size_t)(b * 256 + q) * 512 + 128 + h * 32];
        const float4* sv = (const float4*)&g_qkvg[(size_t)(b * 256 + q) * 512 + 256 + h * 32];
        float4* dk = (float4*)&Ks[q * 36];
        float4* dv = (float4*)&Vs[q * 36];
        #pragma unroll
        for (int i = 0; i < 8; i++) { dk[i] = sk[i]; dv[i] = sv[i]; }
    }

    float qv0[32], qv1[32];
    {
        const float* s0 = &g_qkvg[(size_t)(b * 256 + t) * 512 + h * 32];
        const float* s1 = s0 + 128 * 512;
        #pragma unroll
        for (int i = 0; i < 32; i++) {
            qv0[i] = s0[i] * 0.17677669529663687f;
            qv1[i] = s1[i] * 0.17677669529663687f;
        }
    }
    __syncthreads();

    const float* br0  = &bias[((size_t)h * 256 + t) * 256];
    const float* br1  = br0 + (size_t)128 * 256;
    const float* mrow = &mask[(size_t)b * 256];

    float l0 = 0.f, l1 = 0.f;
    float o0[32], o1[32];
    #pragma unroll
    for (int c = 0; c < 32; c++) { o0[c] = 0.f; o1[c] = 0.f; }

    for (int k = 0; k < 256; k += 4) {
        float4 bb0 = *(const float4*)&br0[k];
        float4 bb1 = *(const float4*)&br1[k];
        float4 mm  = *(const float4*)&mrow[k];
        float ba0[4] = { bb0.x, bb0.y, bb0.z, bb0.w };
        float ba1[4] = { bb1.x, bb1.y, bb1.z, bb1.w };
        float ma[4]  = { (mm.x - 1.f) * 1e9f, (mm.y - 1.f) * 1e9f,
                         (mm.z - 1.f) * 1e9f, (mm.w - 1.f) * 1e9f };

        #pragma unroll
        for (int j = 0; j < 4; j++) {
            const float* kr = &Ks[(k + j) * 36];
            float s0 = 0.f, s1 = 0.f;
            #pragma unroll
            for (int c4 = 0; c4 < 8; c4++) {
                float4 kk = *(const float4*)&kr[c4 * 4];
                s0 += qv0[c4*4+0]*kk.x + qv0[c4*4+1]*kk.y + qv0[c4*4+2]*kk.z + qv0[c4*4+3]*kk.w;
                s1 += qv1[c4*4+0]*kk.x + qv1[c4*4+1]*kk.y + qv1[c4*4+2]*kk.z + qv1[c4*4+3]*kk.w;
            }
            s0 += ma[j] + ba0[j];
            s1 += ma[j] + ba1[j];
            float p0 = __expf(s0);
            float p1 = __expf(s1);
            l0 += p0; l1 += p1;

            const float* vr = &Vs[(k + j) * 36];
            #pragma unroll
            for (int c4 = 0; c4 < 8; c4++) {
                float4 vv = *(const float4*)&vr[c4 * 4];
                o0[c4*4+0] += p0 * vv.x; o0[c4*4+1] += p0 * vv.y;
                o0[c4*4+2] += p0 * vv.z; o0[c4*4+3] += p0 * vv.w;
                o1[c4*4+0] += p1 * vv.x; o1[c4*4+1] += p1 * vv.y;
                o1[c4*4+2] += p1 * vv.z; o1[c4*4+3] += p1 * vv.w;
            }
        }
    }

    const float inv0 = 1.0f / l0;
    const float inv1 = 1.0f / l1;
    const float* grow0 = &g_qkvg[(size_t)(b * 256 + t) * 512 + 384 + h * 32];
    const float* grow1 = grow0 + 128 * 512;
    float* or0 = &g_attn[(size_t)(b * 256 + t) * 128 + h * 32];
    float* or1 = or0 + 128 * 128;
    #pragma unroll
    for (int c = 0; c < 32; c++) {
        float gb = gbias[h * 32 + c];
        float g0 = grow0[c] + gb;
        float g1 = grow1[c] + gb;
        or0[c] = o0[c] * inv0 * (1.0f / (1.0f + __expf(-g0)));
        or1[c] = o1[c] * inv1 * (1.0f / (1.0f + __expf(-g1)));
    }
}

// ---------------------------------------------------------------------------
// K3: output projection (tf32 MMA) + transpose + add.
// C[m][n] = sum_k g_attn[m][k] * Wot[k][n];  out[(s*256+b)*128+n] = add + C + bo
// Same tiling as K1 with N=128 (grid.y = 1).
// ---------------------------------------------------------------------------
__global__ __launch_bounds__(256) void gemm_out_tc_kernel(
    const float* __restrict__ bo, const float* __restrict__ add,
    float* __restrict__ out)
{
    extern __shared__ unsigned shm[];
    unsigned* As = shm;                  // [128][A_STRIDE]
    unsigned* Ws = shm + 128 * A_STRIDE; // [64][B_STRIDE]

    const int tid  = threadIdx.x;
    const int lane = tid & 31;
    const int w    = tid >> 5;
    const int g    = lane >> 2;
    const int tig  = lane & 3;
    const int mw   = (w & 3) * 32;
    const int nw   = (w >> 2) * 64;

    const int m0 = blockIdx.x * 128;

    float acc[2][8][4];
    #pragma unroll
    for (int i = 0; i < 2; i++)
        #pragma unroll
        for (int j = 0; j < 8; j++)
            #pragma unroll
            for (int c = 0; c < 4; c++) acc[i][j][c] = 0.f;

    for (int kc = 0; kc < 128; kc += 64) {
        for (int l = tid; l < 2048; l += 256) {
            int r = l >> 4, c4 = (l & 15) << 2;
            float4 v = *(const float4*)&g_attn[(size_t)(m0 + r) * 128 + kc + c4];
            unsigned* d = &As[r * A_STRIDE + c4];
            d[0] = f2tf(v.x); d[1] = f2tf(v.y); d[2] = f2tf(v.z); d[3] = f2tf(v.w);
        }
        for (int l = tid; l < 2048; l += 256) {
            int r = l >> 5, c4 = (l & 31) << 2;
            float4 v = *(const float4*)&g_Wot[(size_t)(kc + r) * 128 + c4];
            unsigned* d = &Ws[r * B_STRIDE + c4];
            d[0] = f2tf(v.x); d[1] = f2tf(v.y); d[2] = f2tf(v.z); d[3] = f2tf(v.w);
        }
        __syncthreads();

        #pragma unroll
        for (int ks = 0; ks < 64; ks += 8) {
            unsigned a[2][4], b[8][2];
            #pragma unroll
            for (int fm = 0; fm < 2; fm++) {
                int r = mw + fm * 16 + g;
                a[fm][0] = As[r * A_STRIDE + ks + tig];
                a[fm][1] = As[(r + 8) * A_STRIDE + ks + tig];
                a[fm][2] = As[r * A_STRIDE + ks + tig + 4];
                a[fm][3] = As[(r + 8) * A_STRIDE + ks + tig + 4];
            }
            #pragma unroll
            for (int fn = 0; fn < 8; fn++) {
                int n = nw + fn * 8 + g;
                b[fn][0] = Ws[(ks + tig) * B_STRIDE + n];
                b[fn][1] = Ws[(ks + tig + 4) * B_STRIDE + n];
            }
            #pragma unroll
            for (int fm = 0; fm < 2; fm++)
                #pragma unroll
                for (int fn = 0; fn < 8; fn++)
                    mma_tf32(acc[fm][fn], a[fm], b[fn]);
        }
        __syncthreads();
    }

    // epilogue: transpose scatter + add + bias
    #pragma unroll
    for (int fm = 0; fm < 2; fm++) {
        int m_lo = m0 + mw + fm * 16 + g;
        #pragma unroll
        for (int fn = 0; fn < 8; fn++) {
            int n = nw + fn * 8 + 2 * tig;
            float bx = bo[n], by = bo[n + 1];
            {
                int m = m_lo;
                int bb = m >> 8, ss = m & 255;
                size_t base = ((size_t)ss * 256 + bb) * 128 + n;
                float2 av = *(const float2*)&add[base];
                float2 r = { acc[fm][fn][0] + bx + av.x, acc[fm][fn][1] + by + av.y };
                *(float2*)&out[base] = r;
            }
            {
                int m = m_lo + 8;
                int bb = m >> 8, ss = m & 255;
                size_t base = ((size_t)ss * 256 + bb) * 128 + n;
                float2 av = *(const float2*)&add[base];
                float2 r = { acc[fm][fn][2] + bx + av.x, acc[fm][fn][3] + by + av.y };
                *(float2*)&out[base] = r;
            }
        }
    }
}

// ---------------------------------------------------------------------------
extern "C" void kernel_launch(void* const* d_in, const int* in_sizes, int n_in,
                              void* d_out, int out_size)
{
    const float* input_qkv = (const float*)d_in[0];   // [1,256,256,128]
    const float* mask      = (const float*)d_in[1];   // [1,256,1,1,256]
    const float* bias      = (const float*)d_in[2];   // [1,1,4,256,256]
    const float* add_to    = (const float*)d_in[3];   // [1,256,256,128]
    const float* W_qkvg    = (const float*)d_in[4];   // [512,128]
    const float* gbias     = (const float*)d_in[5];   // [128]
    const float* W_o       = (const float*)d_in[6];   // [128,128]
    const float* b_o       = (const float*)d_in[7];   // [128]
    float* out = (float*)d_out;

    const int gemm_smem = (128 * A_STRIDE + 64 * B_STRIDE) * 4;  // 69632 B

    // K0: weight transposes (tiny)
    transpose_w_kernel<<<(512*128 + 128*128 + 255) / 256, 256>>>(W_qkvg, W_o);

    // K1: QKVG projection (tf32 tensor cores)
    {
        cudaFuncSetAttribute(gemm_qkvg_tc_kernel,
                             cudaFuncAttributeMaxDynamicSharedMemorySize, gemm_smem);
        dim3 grid(MTOT / 128, 512 / 128);
        gemm_qkvg_tc_kernel<<<grid, 256, gemm_smem>>>(input_qkv);
    }
    // K2: fused attention + gating (72KB dynamic shared)
    {
        cudaFuncSetAttribute(attn_kernel,
                             cudaFuncAttributeMaxDynamicSharedMemorySize, 2 * 256 * 36 * 4);
        dim3 grid(4, 256);
        attn_kernel<<<grid, 128, 2 * 256 * 36 * 4>>>(mask, bias, gbias);
    }
    // K3: output projection (tf32) + transpose + add
    {
        cudaFuncSetAttribute(gemm_out_tc_kernel,
                             cudaFuncAttributeMaxDynamicSharedMemorySize, gemm_smem);
        dim3 grid(MTOT / 128, 1);
        gemm_out_tc_kernel<<<grid, 256, gemm_smem>>>(b_o, add_to, out);
    }
}

// round 6
// speedup vs baseline: 2.0875x; 2.0875x over previous
#include <cuda_runtime.h>

#define MTOT (256*256)

// Scratch (static device arrays — no allocation in kernel_launch)
__device__ float g_qkvg[(size_t)MTOT * 512];  // [m][q|k|v|g], m = b*256+s
__device__ float g_attn[(size_t)MTOT * 128];  // gated attention output [m][hc]
__device__ float g_Wt [512 * 128];            // W_qkvg transposed: [k=128][n=512]
__device__ float g_Wot[128 * 128];            // W_o transposed:    [k=128][n=128]

// ---------------------------------------------------------------------------
// helpers: tf32 convert + m16n8k8 tf32 MMA
// ---------------------------------------------------------------------------
__device__ __forceinline__ unsigned f2tf(float x) {
    unsigned u;
    asm("cvt.rna.tf32.f32 %0, %1;" : "=r"(u) : "f"(x));
    return u;
}
__device__ __forceinline__ float f2tff(float x) { return __uint_as_float(f2tf(x)); }

__device__ __forceinline__ void mma_tf32(float* d, const unsigned* a, const unsigned* b) {
    asm volatile(
        "mma.sync.aligned.m16n8k8.row.col.f32.tf32.tf32.f32 "
        "{%0,%1,%2,%3}, {%4,%5,%6,%7}, {%8,%9}, {%0,%1,%2,%3};"
        : "+f"(d[0]), "+f"(d[1]), "+f"(d[2]), "+f"(d[3])
        : "r"(a[0]), "r"(a[1]), "r"(a[2]), "r"(a[3]),
          "r"(b[0]), "r"(b[1]));
}

// ---------------------------------------------------------------------------
// K0: transpose the two weight matrices.
// ---------------------------------------------------------------------------
__global__ __launch_bounds__(256) void transpose_w_kernel(
    const float* __restrict__ W, const float* __restrict__ Wo)
{
    int idx = blockIdx.x * 256 + threadIdx.x;
    if (idx < 512 * 128) {
        int k = idx >> 9;
        int n = idx & 511;
        g_Wt[idx] = W[n * 128 + k];
    }
    int idx2 = idx - 512 * 128;
    if (idx2 >= 0 && idx2 < 128 * 128) {
        int k = idx2 >> 7;
        int n = idx2 & 127;
        g_Wot[idx2] = Wo[n * 128 + k];
    }
}

// ---------------------------------------------------------------------------
// K1: QKVG projection (fp32, conflict-free — proven R4 version).
// ---------------------------------------------------------------------------
__global__ __launch_bounds__(256) void gemm_qkvg_kernel(const float* __restrict__ X)
{
    __shared__ float Xs[64][68];
    __shared__ float Ws[64][68];

    const int tx = threadIdx.x & 15;
    const int ty = threadIdx.x >> 4;
    const int m0 = blockIdx.x * 64;
    const int n0 = blockIdx.y * 64;

    float acc[4][4] = {};

    for (int kc = 0; kc < 128; kc += 64) {
        for (int l = threadIdx.x; l < 1024; l += 256) {
            int r = l >> 4, c4 = (l & 15) << 2;
            *(float4*)&Xs[r][c4] = *(const float4*)&X[(size_t)(m0 + r) * 128 + kc + c4];
        }
        for (int l = threadIdx.x; l < 1024; l += 256) {
            int r = l >> 4, c4 = (l & 15) << 2;
            *(float4*)&Ws[r][c4] = *(const float4*)&g_Wt[(size_t)(kc + r) * 512 + n0 + c4];
        }
        __syncthreads();

        #pragma unroll
        for (int k = 0; k < 64; k += 4) {
            float4 av[4], bv[4];
            #pragma unroll
            for (int i = 0; i < 4; i++) av[i] = *(const float4*)&Xs[ty * 4 + i][k];
            #pragma unroll
            for (int j = 0; j < 4; j++) bv[j] = *(const float4*)&Ws[k + j][tx * 4];
            #pragma unroll
            for (int i = 0; i < 4; i++) {
                acc[i][0] += av[i].x * bv[0].x + av[i].y * bv[1].x + av[i].z * bv[2].x + av[i].w * bv[3].x;
                acc[i][1] += av[i].x * bv[0].y + av[i].y * bv[1].y + av[i].z * bv[2].y + av[i].w * bv[3].y;
                acc[i][2] += av[i].x * bv[0].z + av[i].y * bv[1].z + av[i].z * bv[2].z + av[i].w * bv[3].z;
                acc[i][3] += av[i].x * bv[0].w + av[i].y * bv[1].w + av[i].z * bv[2].w + av[i].w * bv[3].w;
            }
        }
        __syncthreads();
    }

    #pragma unroll
    for (int i = 0; i < 4; i++) {
        float4 r;
        r.x = acc[i][0]; r.y = acc[i][1]; r.z = acc[i][2]; r.w = acc[i][3];
        *(float4*)&g_qkvg[(size_t)(m0 + ty * 4 + i) * 512 + n0 + tx * 4] = r;
    }
}

// ---------------------------------------------------------------------------
// K2: tensor-core fused attention.  Block = (h, b), 256 threads = 8 warps.
// Warp w owns query rows q0=32w..q0+31.  Zero block-level syncs in the k-loop:
// P tiles are warp-private smem.  All MMA fragment LDS patterns are
// bank-conflict-free by stride construction (Ks stride 36, VsT stride 268,
// P stride 36).
// smem (floats): Ks[256*36] | VsT[32*268] | Ps[256*36] | madd[256]
// ---------------------------------------------------------------------------
#define KS_STRIDE 36
#define VT_STRIDE 268

__global__ __launch_bounds__(256) void attn_tc_kernel(
    const float* __restrict__ mask, const float* __restrict__ bias,
    const float* __restrict__ gbias)
{
    extern __shared__ float sh[];
    float* Ks   = sh;                           // [256][36]  K rows, tf32
    float* VsT  = sh + 256 * KS_STRIDE;         // [32][268]  V transposed, tf32
    float* Ps   = VsT + 32 * VT_STRIDE;         // [256][36]  Q staging, then P
    float* madd = Ps + 256 * KS_STRIDE;         // [256] (mask-1)*1e9

    const int h = blockIdx.x;
    const int b = blockIdx.y;
    const int tid  = threadIdx.x;
    const int lane = tid & 31;
    const int w    = tid >> 5;
    const int g    = lane >> 2;
    const int tig  = lane & 3;
    const int q0   = w * 32;

    // ---- stage: each thread handles global row `tid` ----
    {
        const float* base = &g_qkvg[(size_t)(b * 256 + tid) * 512 + h * 32];
        // K rows -> Ks[tid][c] (tf32)
        #pragma unroll
        for (int i = 0; i < 8; i++) {
            float4 v = *(const float4*)&base[128 + i * 4];
            float* d = &Ks[tid * KS_STRIDE + i * 4];
            d[0] = f2tff(v.x); d[1] = f2tff(v.y); d[2] = f2tff(v.z); d[3] = f2tff(v.w);
        }
        // V rows -> VsT[c][tid] (tf32, transposed scatter)
        #pragma unroll
        for (int i = 0; i < 8; i++) {
            float4 v = *(const float4*)&base[256 + i * 4];
            VsT[(i * 4 + 0) * VT_STRIDE + tid] = f2tff(v.x);
            VsT[(i * 4 + 1) * VT_STRIDE + tid] = f2tff(v.y);
            VsT[(i * 4 + 2) * VT_STRIDE + tid] = f2tff(v.z);
            VsT[(i * 4 + 3) * VT_STRIDE + tid] = f2tff(v.w);
        }
        // Q rows (scaled) -> Ps[tid][c] (tf32), temporary
        #pragma unroll
        for (int i = 0; i < 8; i++) {
            float4 v = *(const float4*)&base[i * 4];
            float* d = &Ps[tid * KS_STRIDE + i * 4];
            d[0] = f2tff(v.x * 0.17677669529663687f);
            d[1] = f2tff(v.y * 0.17677669529663687f);
            d[2] = f2tff(v.z * 0.17677669529663687f);
            d[3] = f2tff(v.w * 0.17677669529663687f);
        }
        madd[tid] = (mask[(size_t)b * 256 + tid] - 1.0f) * 1e9f;
    }
    __syncthreads();

    // ---- Q fragments to registers (warp reads only its own rows) ----
    unsigned Qa[2][4][4];   // [mfrag][kstep][reg]
    #pragma unroll
    for (int mf = 0; mf < 2; mf++) {
        int r = q0 + 16 * mf + g;
        #pragma unroll
        for (int ks = 0; ks < 4; ks++) {
            Qa[mf][ks][0] = __float_as_uint(Ps[r * KS_STRIDE + 8 * ks + tig]);
            Qa[mf][ks][1] = __float_as_uint(Ps[(r + 8) * KS_STRIDE + 8 * ks + tig]);
            Qa[mf][ks][2] = __float_as_uint(Ps[r * KS_STRIDE + 8 * ks + tig + 4]);
            Qa[mf][ks][3] = __float_as_uint(Ps[(r + 8) * KS_STRIDE + 8 * ks + tig + 4]);
        }
    }
    __syncwarp();

    float Oacc[2][4][4];
    #pragma unroll
    for (int i = 0; i < 2; i++)
        #pragma unroll
        for (int j = 0; j < 4; j++)
            #pragma unroll
            for (int c = 0; c < 4; c++) Oacc[i][j][c] = 0.f;
    float lsum[4] = {0.f, 0.f, 0.f, 0.f};

    float* Pw = Ps + q0 * KS_STRIDE;   // warp-private [32][36]

    const float* biasw = &bias[((size_t)h * 256 + q0) * 256];

    for (int k0 = 0; k0 < 256; k0 += 32) {
        // ---- S = Q K^T (m=32 q, n=32 k-cols, k=32 c) ----
        float Sacc[2][4][4];
        #pragma unroll
        for (int i = 0; i < 2; i++)
            #pragma unroll
            for (int j = 0; j < 4; j++)
                #pragma unroll
                for (int c = 0; c < 4; c++) Sacc[i][j][c] = 0.f;

        #pragma unroll
        for (int ks = 0; ks < 4; ks++) {
            unsigned bf[4][2];
            #pragma unroll
            for (int nf = 0; nf < 4; nf++) {
                int krow = k0 + 8 * nf + g;
                bf[nf][0] = __float_as_uint(Ks[krow * KS_STRIDE + 8 * ks + tig]);
                bf[nf][1] = __float_as_uint(Ks[krow * KS_STRIDE + 8 * ks + tig + 4]);
            }
            #pragma unroll
            for (int mf = 0; mf < 2; mf++)
                #pragma unroll
                for (int nf = 0; nf < 4; nf++)
                    mma_tf32(Sacc[mf][nf], Qa[mf][ks], bf[nf]);
        }

        // ---- exp(S + mask + bias), accumulate row sums, store P (tf32) ----
        #pragma unroll
        for (int nf = 0; nf < 4; nf++) {
            int col = k0 + 8 * nf + 2 * tig;
            float2 md = *(const float2*)&madd[col];
            #pragma unroll
            for (int mf = 0; mf < 2; mf++) {
                int rloc = 16 * mf + g;
                float2 bz0 = *(const float2*)&biasw[(size_t)rloc * 256 + col];
                float2 bz1 = *(const float2*)&biasw[(size_t)(rloc + 8) * 256 + col];
                float p00 = __expf(Sacc[mf][nf][0] + md.x + bz0.x);
                float p01 = __expf(Sacc[mf][nf][1] + md.y + bz0.y);
                float p10 = __expf(Sacc[mf][nf][2] + md.x + bz1.x);
                float p11 = __expf(Sacc[mf][nf][3] + md.y + bz1.y);
                lsum[mf * 2 + 0] += p00 + p01;
                lsum[mf * 2 + 1] += p10 + p11;
                float2 s0 = { f2tff(p00), f2tff(p01) };
                float2 s1 = { f2tff(p10), f2tff(p11) };
                *(float2*)&Pw[rloc * KS_STRIDE + 8 * nf + 2 * tig] = s0;
                *(float2*)&Pw[(rloc + 8) * KS_STRIDE + 8 * nf + 2 * tig] = s1;
            }
        }
        __syncwarp();

        // ---- O += P V  (m=32 q, n=32 c, k=32 kk) ----
        #pragma unroll
        for (int ks = 0; ks < 4; ks++) {
            unsigned af[2][4], bf[4][2];
            #pragma unroll
            for (int mf = 0; mf < 2; mf++) {
                int rloc = 16 * mf + g;
                af[mf][0] = __float_as_uint(Pw[rloc * KS_STRIDE + 8 * ks + tig]);
                af[mf][1] = __float_as_uint(Pw[(rloc + 8) * KS_STRIDE + 8 * ks + tig]);
                af[mf][2] = __float_as_uint(Pw[rloc * KS_STRIDE + 8 * ks + tig + 4]);
                af[mf][3] = __float_as_uint(Pw[(rloc + 8) * KS_STRIDE + 8 * ks + tig + 4]);
            }
            #pragma unroll
            for (int nf = 0; nf < 4; nf++) {
                bf[nf][0] = __float_as_uint(VsT[(8 * nf + g) * VT_STRIDE + k0 + 8 * ks + tig]);
                bf[nf][1] = __float_as_uint(VsT[(8 * nf + g) * VT_STRIDE + k0 + 8 * ks + tig + 4]);
            }
            #pragma unroll
            for (int mf = 0; mf < 2; mf++)
                #pragma unroll
                for (int nf = 0; nf < 4; nf++)
                    mma_tf32(Oacc[mf][nf], af[mf], bf[nf]);
        }
        __syncwarp();   // before next iteration overwrites Pw
    }

    // ---- row-sum reduction across the quad (lanes share g) ----
    float inv[4];
    #pragma unroll
    for (int j = 0; j < 4; j++) {
        float l = lsum[j];
        l += __shfl_xor_sync(0xffffffff, l, 1);
        l += __shfl_xor_sync(0xffffffff, l, 2);
        inv[j] = 1.0f / l;
    }

    // ---- epilogue: normalize, sigmoid gate, store ----
    #pragma unroll
    for (int mf = 0; mf < 2; mf++) {
        #pragma unroll
        for (int half = 0; half < 2; half++) {
            int r = q0 + 16 * mf + g + half * 8;
            float iv = inv[mf * 2 + half];
            const float* grow = &g_qkvg[(size_t)(b * 256 + r) * 512 + 384 + h * 32];
            float* orow = &g_attn[(size_t)(b * 256 + r) * 128 + h * 32];
            #pragma unroll
            for (int nf = 0; nf < 4; nf++) {
                int c = 8 * nf + 2 * tig;
                float2 gg = *(const float2*)&grow[c];
                float2 gb = *(const float2*)&gbias[h * 32 + c];
                float ox = Oacc[mf][nf][half * 2 + 0] * iv;
                float oy = Oacc[mf][nf][half * 2 + 1] * iv;
                float2 res;
                res.x = ox * (1.0f / (1.0f + __expf(-(gg.x + gb.x))));
                res.y = oy * (1.0f / (1.0f + __expf(-(gg.y + gb.y))));
                *(float2*)&orow[c] = res;
            }
        }
    }
}

// ---------------------------------------------------------------------------
// K3: output projection (tf32 MMA) + transpose + add — proven R5 version.
// ---------------------------------------------------------------------------
#define A_STRIDE 68
#define B_STRIDE 136

__global__ __launch_bounds__(256) void gemm_out_tc_kernel(
    const float* __restrict__ bo, const float* __restrict__ add,
    float* __restrict__ out)
{
    extern __shared__ unsigned shm[];
    unsigned* As = shm;                  // [128][A_STRIDE]
    unsigned* Ws = shm + 128 * A_STRIDE; // [64][B_STRIDE]

    const int tid  = threadIdx.x;
    const int lane = tid & 31;
    const int w    = tid >> 5;
    const int g    = lane >> 2;
    const int tig  = lane & 3;
    const int mw   = (w & 3) * 32;
    const int nw   = (w >> 2) * 64;

    const int m0 = blockIdx.x * 128;

    float acc[2][8][4];
    #pragma unroll
    for (int i = 0; i < 2; i++)
        #pragma unroll
        for (int j = 0; j < 8; j++)
            #pragma unroll
            for (int c = 0; c < 4; c++) acc[i][j][c] = 0.f;

    for (int kc = 0; kc < 128; kc += 64) {
        for (int l = tid; l < 2048; l += 256) {
            int r = l >> 4, c4 = (l & 15) << 2;
            float4 v = *(const float4*)&g_attn[(size_t)(m0 + r) * 128 + kc + c4];
            unsigned* d = &As[r * A_STRIDE + c4];
            d[0] = f2tf(v.x); d[1] = f2tf(v.y); d[2] = f2tf(v.z); d[3] = f2tf(v.w);
        }
        for (int l = tid; l < 2048; l += 256) {
            int r = l >> 5, c4 = (l & 31) << 2;
            float4 v = *(const float4*)&g_Wot[(size_t)(kc + r) * 128 + c4];
            unsigned* d = &Ws[r * B_STRIDE + c4];
            d[0] = f2tf(v.x); d[1] = f2tf(v.y); d[2] = f2tf(v.z); d[3] = f2tf(v.w);
        }
        __syncthreads();

        #pragma unroll
        for (int ks = 0; ks < 64; ks += 8) {
            unsigned a[2][4], b[8][2];
            #pragma unroll
            for (int fm = 0; fm < 2; fm++) {
                int r = mw + fm * 16 + g;
                a[fm][0] = As[r * A_STRIDE + ks + tig];
                a[fm][1] = As[(r + 8) * A_STRIDE + ks + tig];
                a[fm][2] = As[r * A_STRIDE + ks + tig + 4];
                a[fm][3] = As[(r + 8) * A_STRIDE + ks + tig + 4];
            }
            #pragma unroll
            for (int fn = 0; fn < 8; fn++) {
                int n = nw + fn * 8 + g;
                b[fn][0] = Ws[(ks + tig) * B_STRIDE + n];
                b[fn][1] = Ws[(ks + tig + 4) * B_STRIDE + n];
            }
            #pragma unroll
            for (int fm = 0; fm < 2; fm++)
                #pragma unroll
                for (int fn = 0; fn < 8; fn++)
                    mma_tf32(acc[fm][fn], a[fm], b[fn]);
        }
        __syncthreads();
    }

    #pragma unroll
    for (int fm = 0; fm < 2; fm++) {
        int m_lo = m0 + mw + fm * 16 + g;
        #pragma unroll
        for (int fn = 0; fn < 8; fn++) {
            int n = nw + fn * 8 + 2 * tig;
            float bx = bo[n], by = bo[n + 1];
            {
                int m = m_lo;
                int bb = m >> 8, ss = m & 255;
                size_t base = ((size_t)ss * 256 + bb) * 128 + n;
                float2 av = *(const float2*)&add[base];
                float2 r = { acc[fm][fn][0] + bx + av.x, acc[fm][fn][1] + by + av.y };
                *(float2*)&out[base] = r;
            }
            {
                int m = m_lo + 8;
                int bb = m >> 8, ss = m & 255;
                size_t base = ((size_t)ss * 256 + bb) * 128 + n;
                float2 av = *(const float2*)&add[base];
                float2 r = { acc[fm][fn][2] + bx + av.x, acc[fm][fn][3] + by + av.y };
                *(float2*)&out[base] = r;
            }
        }
    }
}

// ---------------------------------------------------------------------------
extern "C" void kernel_launch(void* const* d_in, const int* in_sizes, int n_in,
                              void* d_out, int out_size)
{
    const float* input_qkv = (const float*)d_in[0];
    const float* mask      = (const float*)d_in[1];
    const float* bias      = (const float*)d_in[2];
    const float* add_to    = (const float*)d_in[3];
    const float* W_qkvg    = (const float*)d_in[4];
    const float* gbias     = (const float*)d_in[5];
    const float* W_o       = (const float*)d_in[6];
    const float* b_o       = (const float*)d_in[7];
    float* out = (float*)d_out;

    // K0: weight transposes (tiny)
    transpose_w_kernel<<<(512*128 + 128*128 + 255) / 256, 256>>>(W_qkvg, W_o);

    // K1: QKVG projection (fp32, proven)
    {
        dim3 grid(MTOT / 64, 512 / 64);
        gemm_qkvg_kernel<<<grid, 256>>>(input_qkv);
    }
    // K2: tensor-core fused attention
    {
        const int smem = (256 * KS_STRIDE + 32 * VT_STRIDE + 256 * KS_STRIDE + 256) * 4;
        cudaFuncSetAttribute(attn_tc_kernel,
                             cudaFuncAttributeMaxDynamicSharedMemorySize, smem);
        dim3 grid(4, 256);
        attn_tc_kernel<<<grid, 256, smem>>>(mask, bias, gbias);
    }
    // K3: output projection (tf32) + transpose + add (proven)
    {
        const int gemm_smem = (128 * A_STRIDE + 64 * B_STRIDE) * 4;
        cudaFuncSetAttribute(gemm_out_tc_kernel,
                             cudaFuncAttributeMaxDynamicSharedMemorySize, gemm_smem);
        dim3 grid(MTOT / 128, 1);
        gemm_out_tc_kernel<<<grid, 256, gemm_smem>>>(b_o, add_to, out);
    }
}

// round 7
// speedup vs baseline: 2.8228x; 1.3522x over previous
#include <cuda_runtime.h>

#define MTOT (256*256)

// Scratch (static device arrays — no allocation in kernel_launch)
__device__ float g_qkvg[(size_t)MTOT * 512];  // [m][q|k|v|g], m = b*256+s
__device__ float g_attn[(size_t)MTOT * 128];  // gated attention output [m][hc]
__device__ float g_Wt [512 * 128];            // W_qkvg transposed: [k=128][n=512]
__device__ float g_Wot[128 * 128];            // W_o transposed:    [k=128][n=128]

// ---------------------------------------------------------------------------
// helpers: tf32 convert + m16n8k8 tf32 MMA
// ---------------------------------------------------------------------------
__device__ __forceinline__ unsigned f2tf(float x) {
    unsigned u;
    asm("cvt.rna.tf32.f32 %0, %1;" : "=r"(u) : "f"(x));
    return u;
}
__device__ __forceinline__ float f2tff(float x) { return __uint_as_float(f2tf(x)); }

__device__ __forceinline__ void mma_tf32(float* d, const unsigned* a, const unsigned* b) {
    asm volatile(
        "mma.sync.aligned.m16n8k8.row.col.f32.tf32.tf32.f32 "
        "{%0,%1,%2,%3}, {%4,%5,%6,%7}, {%8,%9}, {%0,%1,%2,%3};"
        : "+f"(d[0]), "+f"(d[1]), "+f"(d[2]), "+f"(d[3])
        : "r"(a[0]), "r"(a[1]), "r"(a[2]), "r"(a[3]),
          "r"(b[0]), "r"(b[1]));
}

// ---------------------------------------------------------------------------
// K0: transpose the two weight matrices.
// ---------------------------------------------------------------------------
__global__ __launch_bounds__(256) void transpose_w_kernel(
    const float* __restrict__ W, const float* __restrict__ Wo)
{
    int idx = blockIdx.x * 256 + threadIdx.x;
    if (idx < 512 * 128) {
        int k = idx >> 9;
        int n = idx & 511;
        g_Wt[idx] = W[n * 128 + k];
    }
    int idx2 = idx - 512 * 128;
    if (idx2 >= 0 && idx2 < 128 * 128) {
        int k = idx2 >> 7;
        int n = idx2 & 127;
        g_Wot[idx2] = Wo[n * 128 + k];
    }
}

// ---------------------------------------------------------------------------
// K1: QKVG projection, tf32 MMA, A-resident + double-buffered B.
// Block = 128 m-rows x full N=512 (4 chunks of 128).  Grid = 512 blocks.
// smem: As[128][132] (full K=128, tf32) + Bs[2][128][136].
// 8 warps: mw = (w&3)*32, nw = (w>>2)*64 within the 128-wide n-chunk.
// ---------------------------------------------------------------------------
#define A2_STRIDE 132
#define B_STRIDE  136

__global__ __launch_bounds__(256, 1) void gemm_qkvg_tc_kernel(const float* __restrict__ X)
{
    extern __shared__ unsigned shm[];
    unsigned* As = shm;                         // [128][A2_STRIDE]
    unsigned* Bs = shm + 128 * A2_STRIDE;       // [2][128][B_STRIDE]

    const int tid  = threadIdx.x;
    const int lane = tid & 31;
    const int w    = tid >> 5;
    const int g    = lane >> 2;
    const int tig  = lane & 3;
    const int mw   = (w & 3) * 32;
    const int nw   = (w >> 2) * 64;

    const int m0 = blockIdx.x * 128;

    // ---- stage A once: 128 rows x 128 k (tf32) ----
    for (int l = tid; l < 4096; l += 256) {
        int r = l >> 5, c4 = (l & 31) << 2;
        float4 v = *(const float4*)&X[(size_t)(m0 + r) * 128 + c4];
        unsigned* d = &As[r * A2_STRIDE + c4];
        d[0] = f2tf(v.x); d[1] = f2tf(v.y); d[2] = f2tf(v.z); d[3] = f2tf(v.w);
    }
    // ---- stage B chunk 0 ----
    for (int l = tid; l < 4096; l += 256) {
        int r = l >> 5, c4 = (l & 31) << 2;
        float4 v = *(const float4*)&g_Wt[(size_t)r * 512 + c4];
        unsigned* d = &Bs[r * B_STRIDE + c4];
        d[0] = f2tf(v.x); d[1] = f2tf(v.y); d[2] = f2tf(v.z); d[3] = f2tf(v.w);
    }
    __syncthreads();

    int cur = 0;
    for (int chunk = 0; chunk < 4; chunk++) {
        // prefetch next B chunk into registers (overlaps MMA below)
        float4 breg[16];
        if (chunk < 3) {
            int n0n = (chunk + 1) * 128;
            #pragma unroll
            for (int i = 0; i < 16; i++) {
                int l = tid + i * 256;
                int r = l >> 5, c4 = (l & 31) << 2;
                breg[i] = *(const float4*)&g_Wt[(size_t)r * 512 + n0n + c4];
            }
        }

        // ---- MMA: 128x128 tile over K=128 ----
        float acc[2][8][4];
        #pragma unroll
        for (int i = 0; i < 2; i++)
            #pragma unroll
            for (int j = 0; j < 8; j++)
                #pragma unroll
                for (int c = 0; c < 4; c++) acc[i][j][c] = 0.f;

        const unsigned* Bc = &Bs[cur * 128 * B_STRIDE];
        #pragma unroll
        for (int ks = 0; ks < 128; ks += 8) {
            unsigned a[2][4], b[8][2];
            #pragma unroll
            for (int fm = 0; fm < 2; fm++) {
                int r = mw + fm * 16 + g;
                a[fm][0] = As[r * A2_STRIDE + ks + tig];
                a[fm][1] = As[(r + 8) * A2_STRIDE + ks + tig];
                a[fm][2] = As[r * A2_STRIDE + ks + tig + 4];
                a[fm][3] = As[(r + 8) * A2_STRIDE + ks + tig + 4];
            }
            #pragma unroll
            for (int fn = 0; fn < 8; fn++) {
                int n = nw + fn * 8 + g;
                b[fn][0] = Bc[(ks + tig) * B_STRIDE + n];
                b[fn][1] = Bc[(ks + tig + 4) * B_STRIDE + n];
            }
            #pragma unroll
            for (int fm = 0; fm < 2; fm++)
                #pragma unroll
                for (int fn = 0; fn < 8; fn++)
                    mma_tf32(acc[fm][fn], a[fm], b[fn]);
        }

        // ---- epilogue for this chunk ----
        int n0c = chunk * 128;
        #pragma unroll
        for (int fm = 0; fm < 2; fm++) {
            int row = m0 + mw + fm * 16 + g;
            #pragma unroll
            for (int fn = 0; fn < 8; fn++) {
                int col = n0c + nw + fn * 8 + 2 * tig;
                float2 lo = { acc[fm][fn][0], acc[fm][fn][1] };
                float2 hi = { acc[fm][fn][2], acc[fm][fn][3] };
                *(float2*)&g_qkvg[(size_t)row * 512 + col] = lo;
                *(float2*)&g_qkvg[(size_t)(row + 8) * 512 + col] = hi;
            }
        }

        // ---- commit prefetched chunk into the other buffer ----
        if (chunk < 3) {
            unsigned* Bn = &Bs[(cur ^ 1) * 128 * B_STRIDE];
            #pragma unroll
            for (int i = 0; i < 16; i++) {
                int l = tid + i * 256;
                int r = l >> 5, c4 = (l & 31) << 2;
                unsigned* d = &Bn[r * B_STRIDE + c4];
                d[0] = f2tf(breg[i].x); d[1] = f2tf(breg[i].y);
                d[2] = f2tf(breg[i].z); d[3] = f2tf(breg[i].w);
            }
            __syncthreads();
            cur ^= 1;
        }
    }
}

// ---------------------------------------------------------------------------
// K2: tensor-core fused attention (proven R6 version).
// ---------------------------------------------------------------------------
#define KS_STRIDE 36
#define VT_STRIDE 268

__global__ __launch_bounds__(256) void attn_tc_kernel(
    const float* __restrict__ mask, const float* __restrict__ bias,
    const float* __restrict__ gbias)
{
    extern __shared__ float sh[];
    float* Ks   = sh;                           // [256][36]
    float* VsT  = sh + 256 * KS_STRIDE;         // [32][268]
    float* Ps   = VsT + 32 * VT_STRIDE;         // [256][36]
    float* madd = Ps + 256 * KS_STRIDE;         // [256]

    const int h = blockIdx.x;
    const int b = blockIdx.y;
    const int tid  = threadIdx.x;
    const int lane = tid & 31;
    const int w    = tid >> 5;
    const int g    = lane >> 2;
    const int tig  = lane & 3;
    const int q0   = w * 32;

    {
        const float* base = &g_qkvg[(size_t)(b * 256 + tid) * 512 + h * 32];
        #pragma unroll
        for (int i = 0; i < 8; i++) {
            float4 v = *(const float4*)&base[128 + i * 4];
            float* d = &Ks[tid * KS_STRIDE + i * 4];
            d[0] = f2tff(v.x); d[1] = f2tff(v.y); d[2] = f2tff(v.z); d[3] = f2tff(v.w);
        }
        #pragma unroll
        for (int i = 0; i < 8; i++) {
            float4 v = *(const float4*)&base[256 + i * 4];
            VsT[(i * 4 + 0) * VT_STRIDE + tid] = f2tff(v.x);
            VsT[(i * 4 + 1) * VT_STRIDE + tid] = f2tff(v.y);
            VsT[(i * 4 + 2) * VT_STRIDE + tid] = f2tff(v.z);
            VsT[(i * 4 + 3) * VT_STRIDE + tid] = f2tff(v.w);
        }
        #pragma unroll
        for (int i = 0; i < 8; i++) {
            float4 v = *(const float4*)&base[i * 4];
            float* d = &Ps[tid * KS_STRIDE + i * 4];
            d[0] = f2tff(v.x * 0.17677669529663687f);
            d[1] = f2tff(v.y * 0.17677669529663687f);
            d[2] = f2tff(v.z * 0.17677669529663687f);
            d[3] = f2tff(v.w * 0.17677669529663687f);
        }
        madd[tid] = (mask[(size_t)b * 256 + tid] - 1.0f) * 1e9f;
    }
    __syncthreads();

    unsigned Qa[2][4][4];
    #pragma unroll
    for (int mf = 0; mf < 2; mf++) {
        int r = q0 + 16 * mf + g;
        #pragma unroll
        for (int ks = 0; ks < 4; ks++) {
            Qa[mf][ks][0] = __float_as_uint(Ps[r * KS_STRIDE + 8 * ks + tig]);
            Qa[mf][ks][1] = __float_as_uint(Ps[(r + 8) * KS_STRIDE + 8 * ks + tig]);
            Qa[mf][ks][2] = __float_as_uint(Ps[r * KS_STRIDE + 8 * ks + tig + 4]);
            Qa[mf][ks][3] = __float_as_uint(Ps[(r + 8) * KS_STRIDE + 8 * ks + tig + 4]);
        }
    }
    __syncwarp();

    float Oacc[2][4][4];
    #pragma unroll
    for (int i = 0; i < 2; i++)
        #pragma unroll
        for (int j = 0; j < 4; j++)
            #pragma unroll
            for (int c = 0; c < 4; c++) Oacc[i][j][c] = 0.f;
    float lsum[4] = {0.f, 0.f, 0.f, 0.f};

    float* Pw = Ps + q0 * KS_STRIDE;
    const float* biasw = &bias[((size_t)h * 256 + q0) * 256];

    for (int k0 = 0; k0 < 256; k0 += 32) {
        float Sacc[2][4][4];
        #pragma unroll
        for (int i = 0; i < 2; i++)
            #pragma unroll
            for (int j = 0; j < 4; j++)
                #pragma unroll
                for (int c = 0; c < 4; c++) Sacc[i][j][c] = 0.f;

        #pragma unroll
        for (int ks = 0; ks < 4; ks++) {
            unsigned bf[4][2];
            #pragma unroll
            for (int nf = 0; nf < 4; nf++) {
                int krow = k0 + 8 * nf + g;
                bf[nf][0] = __float_as_uint(Ks[krow * KS_STRIDE + 8 * ks + tig]);
                bf[nf][1] = __float_as_uint(Ks[krow * KS_STRIDE + 8 * ks + tig + 4]);
            }
            #pragma unroll
            for (int mf = 0; mf < 2; mf++)
                #pragma unroll
                for (int nf = 0; nf < 4; nf++)
                    mma_tf32(Sacc[mf][nf], Qa[mf][ks], bf[nf]);
        }

        #pragma unroll
        for (int nf = 0; nf < 4; nf++) {
            int col = k0 + 8 * nf + 2 * tig;
            float2 md = *(const float2*)&madd[col];
            #pragma unroll
            for (int mf = 0; mf < 2; mf++) {
                int rloc = 16 * mf + g;
                float2 bz0 = *(const float2*)&biasw[(size_t)rloc * 256 + col];
                float2 bz1 = *(const float2*)&biasw[(size_t)(rloc + 8) * 256 + col];
                float p00 = __expf(Sacc[mf][nf][0] + md.x + bz0.x);
                float p01 = __expf(Sacc[mf][nf][1] + md.y + bz0.y);
                float p10 = __expf(Sacc[mf][nf][2] + md.x + bz1.x);
                float p11 = __expf(Sacc[mf][nf][3] + md.y + bz1.y);
                lsum[mf * 2 + 0] += p00 + p01;
                lsum[mf * 2 + 1] += p10 + p11;
                float2 s0 = { f2tff(p00), f2tff(p01) };
                float2 s1 = { f2tff(p10), f2tff(p11) };
                *(float2*)&Pw[rloc * KS_STRIDE + 8 * nf + 2 * tig] = s0;
                *(float2*)&Pw[(rloc + 8) * KS_STRIDE + 8 * nf + 2 * tig] = s1;
            }
        }
        __syncwarp();

        #pragma unroll
        for (int ks = 0; ks < 4; ks++) {
            unsigned af[2][4], bf[4][2];
            #pragma unroll
            for (int mf = 0; mf < 2; mf++) {
                int rloc = 16 * mf + g;
                af[mf][0] = __float_as_uint(Pw[rloc * KS_STRIDE + 8 * ks + tig]);
                af[mf][1] = __float_as_uint(Pw[(rloc + 8) * KS_STRIDE + 8 * ks + tig]);
                af[mf][2] = __float_as_uint(Pw[rloc * KS_STRIDE + 8 * ks + tig + 4]);
                af[mf][3] = __float_as_uint(Pw[(rloc + 8) * KS_STRIDE + 8 * ks + tig + 4]);
            }
            #pragma unroll
            for (int nf = 0; nf < 4; nf++) {
                bf[nf][0] = __float_as_uint(VsT[(8 * nf + g) * VT_STRIDE + k0 + 8 * ks + tig]);
                bf[nf][1] = __float_as_uint(VsT[(8 * nf + g) * VT_STRIDE + k0 + 8 * ks + tig + 4]);
            }
            #pragma unroll
            for (int mf = 0; mf < 2; mf++)
                #pragma unroll
                for (int nf = 0; nf < 4; nf++)
                    mma_tf32(Oacc[mf][nf], af[mf], bf[nf]);
        }
        __syncwarp();
    }

    float inv[4];
    #pragma unroll
    for (int j = 0; j < 4; j++) {
        float l = lsum[j];
        l += __shfl_xor_sync(0xffffffff, l, 1);
        l += __shfl_xor_sync(0xffffffff, l, 2);
        inv[j] = 1.0f / l;
    }

    #pragma unroll
    for (int mf = 0; mf < 2; mf++) {
        #pragma unroll
        for (int half = 0; half < 2; half++) {
            int r = q0 + 16 * mf + g + half * 8;
            float iv = inv[mf * 2 + half];
            const float* grow = &g_qkvg[(size_t)(b * 256 + r) * 512 + 384 + h * 32];
            float* orow = &g_attn[(size_t)(b * 256 + r) * 128 + h * 32];
            #pragma unroll
            for (int nf = 0; nf < 4; nf++) {
                int c = 8 * nf + 2 * tig;
                float2 gg = *(const float2*)&grow[c];
                float2 gb = *(const float2*)&gbias[h * 32 + c];
                float ox = Oacc[mf][nf][half * 2 + 0] * iv;
                float oy = Oacc[mf][nf][half * 2 + 1] * iv;
                float2 res;
                res.x = ox * (1.0f / (1.0f + __expf(-(gg.x + gb.x))));
                res.y = oy * (1.0f / (1.0f + __expf(-(gg.y + gb.y))));
                *(float2*)&orow[c] = res;
            }
        }
    }
}

// ---------------------------------------------------------------------------
// K3: output projection (tf32 MMA) + transpose + add (proven R5/R6 version).
// ---------------------------------------------------------------------------
#define A_STRIDE 68

__global__ __launch_bounds__(256) void gemm_out_tc_kernel(
    const float* __restrict__ bo, const float* __restrict__ add,
    float* __restrict__ out)
{
    extern __shared__ unsigned shm[];
    unsigned* As = shm;                  // [128][A_STRIDE]
    unsigned* Ws = shm + 128 * A_STRIDE; // [64][B_STRIDE]

    const int tid  = threadIdx.x;
    const int lane = tid & 31;
    const int w    = tid >> 5;
    const int g    = lane >> 2;
    const int tig  = lane & 3;
    const int mw   = (w & 3) * 32;
    const int nw   = (w >> 2) * 64;

    const int m0 = blockIdx.x * 128;

    float acc[2][8][4];
    #pragma unroll
    for (int i = 0; i < 2; i++)
        #pragma unroll
        for (int j = 0; j < 8; j++)
            #pragma unroll
            for (int c = 0; c < 4; c++) acc[i][j][c] = 0.f;

    for (int kc = 0; kc < 128; kc += 64) {
        for (int l = tid; l < 2048; l += 256) {
            int r = l >> 4, c4 = (l & 15) << 2;
            float4 v = *(const float4*)&g_attn[(size_t)(m0 + r) * 128 + kc + c4];
            unsigned* d = &As[r * A_STRIDE + c4];
            d[0] = f2tf(v.x); d[1] = f2tf(v.y); d[2] = f2tf(v.z); d[3] = f2tf(v.w);
        }
        for (int l = tid; l < 2048; l += 256) {
            int r = l >> 5, c4 = (l & 31) << 2;
            float4 v = *(const float4*)&g_Wot[(size_t)(kc + r) * 128 + c4];
            unsigned* d = &Ws[r * B_STRIDE + c4];
            d[0] = f2tf(v.x); d[1] = f2tf(v.y); d[2] = f2tf(v.z); d[3] = f2tf(v.w);
        }
        __syncthreads();

        #pragma unroll
        for (int ks = 0; ks < 64; ks += 8) {
            unsigned a[2][4], b[8][2];
            #pragma unroll
            for (int fm = 0; fm < 2; fm++) {
                int r = mw + fm * 16 + g;
                a[fm][0] = As[r * A_STRIDE + ks + tig];
                a[fm][1] = As[(r + 8) * A_STRIDE + ks + tig];
                a[fm][2] = As[r * A_STRIDE + ks + tig + 4];
                a[fm][3] = As[(r + 8) * A_STRIDE + ks + tig + 4];
            }
            #pragma unroll
            for (int fn = 0; fn < 8; fn++) {
                int n = nw + fn * 8 + g;
                b[fn][0] = Ws[(ks + tig) * B_STRIDE + n];
                b[fn][1] = Ws[(ks + tig + 4) * B_STRIDE + n];
            }
            #pragma unroll
            for (int fm = 0; fm < 2; fm++)
                #pragma unroll
                for (int fn = 0; fn < 8; fn++)
                    mma_tf32(acc[fm][fn], a[fm], b[fn]);
        }
        __syncthreads();
    }

    #pragma unroll
    for (int fm = 0; fm < 2; fm++) {
        int m_lo = m0 + mw + fm * 16 + g;
        #pragma unroll
        for (int fn = 0; fn < 8; fn++) {
            int n = nw + fn * 8 + 2 * tig;
            float bx = bo[n], by = bo[n + 1];
            {
                int m = m_lo;
                int bb = m >> 8, ss = m & 255;
                size_t base = ((size_t)ss * 256 + bb) * 128 + n;
                float2 av = *(const float2*)&add[base];
                float2 r = { acc[fm][fn][0] + bx + av.x, acc[fm][fn][1] + by + av.y };
                *(float2*)&out[base] = r;
            }
            {
                int m = m_lo + 8;
                int bb = m >> 8, ss = m & 255;
                size_t base = ((size_t)ss * 256 + bb) * 128 + n;
                float2 av = *(const float2*)&add[base];
                float2 r = { acc[fm][fn][2] + bx + av.x, acc[fm][fn][3] + by + av.y };
                *(float2*)&out[base] = r;
            }
        }
    }
}

// ---------------------------------------------------------------------------
extern "C" void kernel_launch(void* const* d_in, const int* in_sizes, int n_in,
                              void* d_out, int out_size)
{
    const float* input_qkv = (const float*)d_in[0];
    const float* mask      = (const float*)d_in[1];
    const float* bias      = (const float*)d_in[2];
    const float* add_to    = (const float*)d_in[3];
    const float* W_qkvg    = (const float*)d_in[4];
    const float* gbias     = (const float*)d_in[5];
    const float* W_o       = (const float*)d_in[6];
    const float* b_o       = (const float*)d_in[7];
    float* out = (float*)d_out;

    // K0: weight transposes (tiny)
    transpose_w_kernel<<<(512*128 + 128*128 + 255) / 256, 256>>>(W_qkvg, W_o);

    // K1: QKVG projection (tf32, A-resident, double-buffered B)
    {
        const int smem = (128 * A2_STRIDE + 2 * 128 * B_STRIDE) * 4;  // 206848 B
        cudaFuncSetAttribute(gemm_qkvg_tc_kernel,
                             cudaFuncAttributeMaxDynamicSharedMemorySize, smem);
        gemm_qkvg_tc_kernel<<<512, 256, smem>>>(input_qkv);
    }
    // K2: tensor-core fused attention
    {
        const int smem = (256 * KS_STRIDE + 32 * VT_STRIDE + 256 * KS_STRIDE + 256) * 4;
        cudaFuncSetAttribute(attn_tc_kernel,
                             cudaFuncAttributeMaxDynamicSharedMemorySize, smem);
        dim3 grid(4, 256);
        attn_tc_kernel<<<grid, 256, smem>>>(mask, bias, gbias);
    }
    // K3: output projection (tf32) + transpose + add
    {
        const int gemm_smem = (128 * A_STRIDE + 64 * B_STRIDE) * 4;
        cudaFuncSetAttribute(gemm_out_tc_kernel,
                             cudaFuncAttributeMaxDynamicSharedMemorySize, gemm_smem);
        gemm_out_tc_kernel<<<512, 256, gemm_smem>>>(b_o, add_to, out);
    }
}

// round 10
// speedup vs baseline: 2.9771x; 1.0547x over previous
#include <cuda_runtime.h>

#define MTOT (256*256)

// Scratch (static device arrays — no allocation in kernel_launch)
__device__ float g_qkvg[(size_t)MTOT * 512];  // [m][q|k|v|g], m = b*256+s
__device__ float g_attn[(size_t)MTOT * 128];  // gated attention output [m][hc]
__device__ float g_Wt [512 * 128];            // W_qkvg transposed: [k=128][n=512]
__device__ float g_Wot[128 * 128];            // W_o transposed:    [k=128][n=128]

// ---------------------------------------------------------------------------
// helpers: tf32 convert + m16n8k8 tf32 MMA
// ---------------------------------------------------------------------------
__device__ __forceinline__ unsigned f2tf(float x) {
    unsigned u;
    asm("cvt.rna.tf32.f32 %0, %1;" : "=r"(u) : "f"(x));
    return u;
}
__device__ __forceinline__ float f2tff(float x) { return __uint_as_float(f2tf(x)); }

__device__ __forceinline__ void mma_tf32(float* d, const unsigned* a, const unsigned* b) {
    asm volatile(
        "mma.sync.aligned.m16n8k8.row.col.f32.tf32.tf32.f32 "
        "{%0,%1,%2,%3}, {%4,%5,%6,%7}, {%8,%9}, {%0,%1,%2,%3};"
        : "+f"(d[0]), "+f"(d[1]), "+f"(d[2]), "+f"(d[3])
        : "r"(a[0]), "r"(a[1]), "r"(a[2]), "r"(a[3]),
          "r"(b[0]), "r"(b[1]));
}

// ---------------------------------------------------------------------------
// K0: transpose the two weight matrices.
// ---------------------------------------------------------------------------
__global__ __launch_bounds__(256) void transpose_w_kernel(
    const float* __restrict__ W, const float* __restrict__ Wo)
{
    int idx = blockIdx.x * 256 + threadIdx.x;
    if (idx < 512 * 128) {
        int k = idx >> 9;
        int n = idx & 511;
        g_Wt[idx] = W[n * 128 + k];
    }
    int idx2 = idx - 512 * 128;
    if (idx2 >= 0 && idx2 < 128 * 128) {
        int k = idx2 >> 7;
        int n = idx2 & 127;
        g_Wot[idx2] = Wo[n * 128 + k];
    }
}

// ---------------------------------------------------------------------------
// K1: QKVG projection, tf32 MMA, 512 threads (16 warps = 4/SMSP).
// Block = 128 m-rows x N=512 in 2 chunks of 256.  Grid = 512 blocks.
// smem: As[128][132] (A-resident, full K=128) + Bs[128][264] (one 256-n chunk).
// Warp tile 32x64: mw=(w&3)*32, nw=(w>>2)*64.
// ---------------------------------------------------------------------------
#define A2_STRIDE 132
#define B2_STRIDE 264

__global__ __launch_bounds__(512, 1) void gemm_qkvg_tc_kernel(const float* __restrict__ X)
{
    extern __shared__ unsigned shm[];
    unsigned* As = shm;                         // [128][A2_STRIDE]
    unsigned* Bs = shm + 128 * A2_STRIDE;       // [128][B2_STRIDE]

    const int tid  = threadIdx.x;
    const int lane = tid & 31;
    const int w    = tid >> 5;          // 0..15
    const int g    = lane >> 2;
    const int tig  = lane & 3;
    const int mw   = (w & 3) * 32;
    const int nw   = (w >> 2) * 64;     // 0,64,128,192 within the 256-wide chunk

    const int m0 = blockIdx.x * 128;

    // ---- stage A once: 128 rows x 128 k (tf32) ----
    for (int l = tid; l < 4096; l += 512) {
        int r = l >> 5, c4 = (l & 31) << 2;
        float4 v = *(const float4*)&X[(size_t)(m0 + r) * 128 + c4];
        unsigned* d = &As[r * A2_STRIDE + c4];
        d[0] = f2tf(v.x); d[1] = f2tf(v.y); d[2] = f2tf(v.z); d[3] = f2tf(v.w);
    }
    // ---- stage B chunk 0: 128 k x 256 n ----
    for (int l = tid; l < 8192; l += 512) {
        int r = l >> 6, c4 = (l & 63) << 2;
        float4 v = *(const float4*)&g_Wt[(size_t)r * 512 + c4];
        unsigned* d = &Bs[r * B2_STRIDE + c4];
        d[0] = f2tf(v.x); d[1] = f2tf(v.y); d[2] = f2tf(v.z); d[3] = f2tf(v.w);
    }
    __syncthreads();

    #pragma unroll
    for (int chunk = 0; chunk < 2; chunk++) {
        float acc[2][8][4];
        #pragma unroll
        for (int i = 0; i < 2; i++)
            #pragma unroll
            for (int j = 0; j < 8; j++)
                #pragma unroll
                for (int c = 0; c < 4; c++) acc[i][j][c] = 0.f;

        #pragma unroll
        for (int ks = 0; ks < 128; ks += 8) {
            unsigned a[2][4], b[8][2];
            #pragma unroll
            for (int fm = 0; fm < 2; fm++) {
                int r = mw + fm * 16 + g;
                a[fm][0] = As[r * A2_STRIDE + ks + tig];
                a[fm][1] = As[(r + 8) * A2_STRIDE + ks + tig];
                a[fm][2] = As[r * A2_STRIDE + ks + tig + 4];
                a[fm][3] = As[(r + 8) * A2_STRIDE + ks + tig + 4];
            }
            #pragma unroll
            for (int fn = 0; fn < 8; fn++) {
                int n = nw + fn * 8 + g;
                b[fn][0] = Bs[(ks + tig) * B2_STRIDE + n];
                b[fn][1] = Bs[(ks + tig + 4) * B2_STRIDE + n];
            }
            #pragma unroll
            for (int fm = 0; fm < 2; fm++)
                #pragma unroll
                for (int fn = 0; fn < 8; fn++)
                    mma_tf32(acc[fm][fn], a[fm], b[fn]);
        }

        // ---- epilogue for this chunk ----
        int n0c = chunk * 256;
        #pragma unroll
        for (int fm = 0; fm < 2; fm++) {
            int row = m0 + mw + fm * 16 + g;
            #pragma unroll
            for (int fn = 0; fn < 8; fn++) {
                int col = n0c + nw + fn * 8 + 2 * tig;
                float2 lo = { acc[fm][fn][0], acc[fm][fn][1] };
                float2 hi = { acc[fm][fn][2], acc[fm][fn][3] };
                *(float2*)&g_qkvg[(size_t)row * 512 + col] = lo;
                *(float2*)&g_qkvg[(size_t)(row + 8) * 512 + col] = hi;
            }
        }

        // ---- restage B for chunk 1 (g_Wt is L2-resident; short gap) ----
        if (chunk == 0) {
            __syncthreads();
            for (int l = tid; l < 8192; l += 512) {
                int r = l >> 6, c4 = (l & 63) << 2;
                float4 v = *(const float4*)&g_Wt[(size_t)r * 512 + 256 + c4];
                unsigned* d = &Bs[r * B2_STRIDE + c4];
                d[0] = f2tf(v.x); d[1] = f2tf(v.y); d[2] = f2tf(v.z); d[3] = f2tf(v.w);
            }
            __syncthreads();
        }
    }
}

// ---------------------------------------------------------------------------
// K2: tensor-core fused attention (proven R6/R7 version).
// ---------------------------------------------------------------------------
#define KS_STRIDE 36
#define VT_STRIDE 268

__global__ __launch_bounds__(256) void attn_tc_kernel(
    const float* __restrict__ mask, const float* __restrict__ bias,
    const float* __restrict__ gbias)
{
    extern __shared__ float sh[];
    float* Ks   = sh;                           // [256][36]
    float* VsT  = sh + 256 * KS_STRIDE;         // [32][268]
    float* Ps   = VsT + 32 * VT_STRIDE;         // [256][36]
    float* madd = Ps + 256 * KS_STRIDE;         // [256]

    const int h = blockIdx.x;
    const int b = blockIdx.y;
    const int tid  = threadIdx.x;
    const int lane = tid & 31;
    const int w    = tid >> 5;
    const int g    = lane >> 2;
    const int tig  = lane & 3;
    const int q0   = w * 32;

    {
        const float* base = &g_qkvg[(size_t)(b * 256 + tid) * 512 + h * 32];
        #pragma unroll
        for (int i = 0; i < 8; i++) {
            float4 v = *(const float4*)&base[128 + i * 4];
            float* d = &Ks[tid * KS_STRIDE + i * 4];
            d[0] = f2tff(v.x); d[1] = f2tff(v.y); d[2] = f2tff(v.z); d[3] = f2tff(v.w);
        }
        #pragma unroll
        for (int i = 0; i < 8; i++) {
            float4 v = *(const float4*)&base[256 + i * 4];
            VsT[(i * 4 + 0) * VT_STRIDE + tid] = f2tff(v.x);
            VsT[(i * 4 + 1) * VT_STRIDE + tid] = f2tff(v.y);
            VsT[(i * 4 + 2) * VT_STRIDE + tid] = f2tff(v.z);
            VsT[(i * 4 + 3) * VT_STRIDE + tid] = f2tff(v.w);
        }
        #pragma unroll
        for (int i = 0; i < 8; i++) {
            float4 v = *(const float4*)&base[i * 4];
            float* d = &Ps[tid * KS_STRIDE + i * 4];
            d[0] = f2tff(v.x * 0.17677669529663687f);
            d[1] = f2tff(v.y * 0.17677669529663687f);
            d[2] = f2tff(v.z * 0.17677669529663687f);
            d[3] = f2tff(v.w * 0.17677669529663687f);
        }
        madd[tid] = (mask[(size_t)b * 256 + tid] - 1.0f) * 1e9f;
    }
    __syncthreads();

    unsigned Qa[2][4][4];
    #pragma unroll
    for (int mf = 0; mf < 2; mf++) {
        int r = q0 + 16 * mf + g;
        #pragma unroll
        for (int ks = 0; ks < 4; ks++) {
            Qa[mf][ks][0] = __float_as_uint(Ps[r * KS_STRIDE + 8 * ks + tig]);
            Qa[mf][ks][1] = __float_as_uint(Ps[(r + 8) * KS_STRIDE + 8 * ks + tig]);
            Qa[mf][ks][2] = __float_as_uint(Ps[r * KS_STRIDE + 8 * ks + tig + 4]);
            Qa[mf][ks][3] = __float_as_uint(Ps[(r + 8) * KS_STRIDE + 8 * ks + tig + 4]);
        }
    }
    __syncwarp();

    float Oacc[2][4][4];
    #pragma unroll
    for (int i = 0; i < 2; i++)
        #pragma unroll
        for (int j = 0; j < 4; j++)
            #pragma unroll
            for (int c = 0; c < 4; c++) Oacc[i][j][c] = 0.f;
    float lsum[4] = {0.f, 0.f, 0.f, 0.f};

    float* Pw = Ps + q0 * KS_STRIDE;
    const float* biasw = &bias[((size_t)h * 256 + q0) * 256];

    for (int k0 = 0; k0 < 256; k0 += 32) {
        float Sacc[2][4][4];
        #pragma unroll
        for (int i = 0; i < 2; i++)
            #pragma unroll
            for (int j = 0; j < 4; j++)
                #pragma unroll
                for (int c = 0; c < 4; c++) Sacc[i][j][c] = 0.f;

        #pragma unroll
        for (int ks = 0; ks < 4; ks++) {
            unsigned bf[4][2];
            #pragma unroll
            for (int nf = 0; nf < 4; nf++) {
                int krow = k0 + 8 * nf + g;
                bf[nf][0] = __float_as_uint(Ks[krow * KS_STRIDE + 8 * ks + tig]);
                bf[nf][1] = __float_as_uint(Ks[krow * KS_STRIDE + 8 * ks + tig + 4]);
            }
            #pragma unroll
            for (int mf = 0; mf < 2; mf++)
                #pragma unroll
                for (int nf = 0; nf < 4; nf++)
                    mma_tf32(Sacc[mf][nf], Qa[mf][ks], bf[nf]);
        }

        #pragma unroll
        for (int nf = 0; nf < 4; nf++) {
            int col = k0 + 8 * nf + 2 * tig;
            float2 md = *(const float2*)&madd[col];
            #pragma unroll
            for (int mf = 0; mf < 2; mf++) {
                int rloc = 16 * mf + g;
                float2 bz0 = *(const float2*)&biasw[(size_t)rloc * 256 + col];
                float2 bz1 = *(const float2*)&biasw[(size_t)(rloc + 8) * 256 + col];
                float p00 = __expf(Sacc[mf][nf][0] + md.x + bz0.x);
                float p01 = __expf(Sacc[mf][nf][1] + md.y + bz0.y);
                float p10 = __expf(Sacc[mf][nf][2] + md.x + bz1.x);
                float p11 = __expf(Sacc[mf][nf][3] + md.y + bz1.y);
                lsum[mf * 2 + 0] += p00 + p01;
                lsum[mf * 2 + 1] += p10 + p11;
                float2 s0 = { f2tff(p00), f2tff(p01) };
                float2 s1 = { f2tff(p10), f2tff(p11) };
                *(float2*)&Pw[rloc * KS_STRIDE + 8 * nf + 2 * tig] = s0;
                *(float2*)&Pw[(rloc + 8) * KS_STRIDE + 8 * nf + 2 * tig] = s1;
            }
        }
        __syncwarp();

        #pragma unroll
        for (int ks = 0; ks < 4; ks++) {
            unsigned af[2][4], bf[4][2];
            #pragma unroll
            for (int mf = 0; mf < 2; mf++) {
                int rloc = 16 * mf + g;
                af[mf][0] = __float_as_uint(Pw[rloc * KS_STRIDE + 8 * ks + tig]);
                af[mf][1] = __float_as_uint(Pw[(rloc + 8) * KS_STRIDE + 8 * ks + tig]);
                af[mf][2] = __float_as_uint(Pw[rloc * KS_STRIDE + 8 * ks + tig + 4]);
                af[mf][3] = __float_as_uint(Pw[(rloc + 8) * KS_STRIDE + 8 * ks + tig + 4]);
            }
            #pragma unroll
            for (int nf = 0; nf < 4; nf++) {
                bf[nf][0] = __float_as_uint(VsT[(8 * nf + g) * VT_STRIDE + k0 + 8 * ks + tig]);
                bf[nf][1] = __float_as_uint(VsT[(8 * nf + g) * VT_STRIDE + k0 + 8 * ks + tig + 4]);
            }
            #pragma unroll
            for (int mf = 0; mf < 2; mf++)
                #pragma unroll
                for (int nf = 0; nf < 4; nf++)
                    mma_tf32(Oacc[mf][nf], af[mf], bf[nf]);
        }
        __syncwarp();
    }

    float inv[4];
    #pragma unroll
    for (int j = 0; j < 4; j++) {
        float l = lsum[j];
        l += __shfl_xor_sync(0xffffffff, l, 1);
        l += __shfl_xor_sync(0xffffffff, l, 2);
        inv[j] = 1.0f / l;
    }

    #pragma unroll
    for (int mf = 0; mf < 2; mf++) {
        #pragma unroll
        for (int half = 0; half < 2; half++) {
            int r = q0 + 16 * mf + g + half * 8;
            float iv = inv[mf * 2 + half];
            const float* grow = &g_qkvg[(size_t)(b * 256 + r) * 512 + 384 + h * 32];
            float* orow = &g_attn[(size_t)(b * 256 + r) * 128 + h * 32];
            #pragma unroll
            for (int nf = 0; nf < 4; nf++) {
                int c = 8 * nf + 2 * tig;
                float2 gg = *(const float2*)&grow[c];
                float2 gb = *(const float2*)&gbias[h * 32 + c];
                float ox = Oacc[mf][nf][half * 2 + 0] * iv;
                float oy = Oacc[mf][nf][half * 2 + 1] * iv;
                float2 res;
                res.x = ox * (1.0f / (1.0f + __expf(-(gg.x + gb.x))));
                res.y = oy * (1.0f / (1.0f + __expf(-(gg.y + gb.y))));
                *(float2*)&orow[c] = res;
            }
        }
    }
}

// ---------------------------------------------------------------------------
// K3: output projection (tf32 MMA) + transpose + add (proven, at DRAM floor).
// ---------------------------------------------------------------------------
#define A_STRIDE 68
#define B_STRIDE 136

__global__ __launch_bounds__(256) void gemm_out_tc_kernel(
    const float* __restrict__ bo, const float* __restrict__ add,
    float* __restrict__ out)
{
    extern __shared__ unsigned shm[];
    unsigned* As = shm;                  // [128][A_STRIDE]
    unsigned* Ws = shm + 128 * A_STRIDE; // [64][B_STRIDE]

    const int tid  = threadIdx.x;
    const int lane = tid & 31;
    const int w    = tid >> 5;
    const int g    = lane >> 2;
    const int tig  = lane & 3;
    const int mw   = (w & 3) * 32;
    const int nw   = (w >> 2) * 64;

    const int m0 = blockIdx.x * 128;

    float acc[2][8][4];
    #pragma unroll
    for (int i = 0; i < 2; i++)
        #pragma unroll
        for (int j = 0; j < 8; j++)
            #pragma unroll
            for (int c = 0; c < 4; c++) acc[i][j][c] = 0.f;

    for (int kc = 0; kc < 128; kc += 64) {
        for (int l = tid; l < 2048; l += 256) {
            int r = l >> 4, c4 = (l & 15) << 2;
            float4 v = *(const float4*)&g_attn[(size_t)(m0 + r) * 128 + kc + c4];
            unsigned* d = &As[r * A_STRIDE + c4];
            d[0] = f2tf(v.x); d[1] = f2tf(v.y); d[2] = f2tf(v.z); d[3] = f2tf(v.w);
        }
        for (int l = tid; l < 2048; l += 256) {
            int r = l >> 5, c4 = (l & 31) << 2;
            float4 v = *(const float4*)&g_Wot[(size_t)(kc + r) * 128 + c4];
            unsigned* d = &Ws[r * B_STRIDE + c4];
            d[0] = f2tf(v.x); d[1] = f2tf(v.y); d[2] = f2tf(v.z); d[3] = f2tf(v.w);
        }
        __syncthreads();

        #pragma unroll
        for (int ks = 0; ks < 64; ks += 8) {
            unsigned a[2][4], b[8][2];
            #pragma unroll
            for (int fm = 0; fm < 2; fm++) {
                int r = mw + fm * 16 + g;
                a[fm][0] = As[r * A_STRIDE + ks + tig];
                a[fm][1] = As[(r + 8) * A_STRIDE + ks + tig];
                a[fm][2] = As[r * A_STRIDE + ks + tig + 4];
                a[fm][3] = As[(r + 8) * A_STRIDE + ks + tig + 4];
            }
            #pragma unroll
            for (int fn = 0; fn < 8; fn++) {
                int n = nw + fn * 8 + g;
                b[fn][0] = Ws[(ks + tig) * B_STRIDE + n];
                b[fn][1] = Ws[(ks + tig + 4) * B_STRIDE + n];
            }
            #pragma unroll
            for (int fm = 0; fm < 2; fm++)
                #pragma unroll
                for (int fn = 0; fn < 8; fn++)
                    mma_tf32(acc[fm][fn], a[fm], b[fn]);
        }
        __syncthreads();
    }

    #pragma unroll
    for (int fm = 0; fm < 2; fm++) {
        int m_lo = m0 + mw + fm * 16 + g;
        #pragma unroll
        for (int fn = 0; fn < 8; fn++) {
            int n = nw + fn * 8 + 2 * tig;
            float bx = bo[n], by = bo[n + 1];
            {
                int m = m_lo;
                int bb = m >> 8, ss = m & 255;
                size_t base = ((size_t)ss * 256 + bb) * 128 + n;
                float2 av = *(const float2*)&add[base];
                float2 r = { acc[fm][fn][0] + bx + av.x, acc[fm][fn][1] + by + av.y };
                *(float2*)&out[base] = r;
            }
            {
                int m = m_lo + 8;
                int bb = m >> 8, ss = m & 255;
                size_t base = ((size_t)ss * 256 + bb) * 128 + n;
                float2 av = *(const float2*)&add[base];
                float2 r = { acc[fm][fn][2] + bx + av.x, acc[fm][fn][3] + by + av.y };
                *(float2*)&out[base] = r;
            }
        }
    }
}

// ---------------------------------------------------------------------------
extern "C" void kernel_launch(void* const* d_in, const int* in_sizes, int n_in,
                              void* d_out, int out_size)
{
    const float* input_qkv = (const float*)d_in[0];
    const float* mask      = (const float*)d_in[1];
    const float* bias      = (const float*)d_in[2];
    const float* add_to    = (const float*)d_in[3];
    const float* W_qkvg    = (const float*)d_in[4];
    const float* gbias     = (const float*)d_in[5];
    const float* W_o       = (const float*)d_in[6];
    const float* b_o       = (const float*)d_in[7];
    float* out = (float*)d_out;

    // K0: weight transposes (tiny)
    transpose_w_kernel<<<(512*128 + 128*128 + 255) / 256, 256>>>(W_qkvg, W_o);

    // K1: QKVG projection (tf32, 512 threads, A-resident)
    {
        const int smem = (128 * A2_STRIDE + 128 * B2_STRIDE) * 4;  // 202752 B
        cudaFuncSetAttribute(gemm_qkvg_tc_kernel,
                             cudaFuncAttributeMaxDynamicSharedMemorySize, smem);
        gemm_qkvg_tc_kernel<<<512, 512, smem>>>(input_qkv);
    }
    // K2: tensor-core fused attention
    {
        const int smem = (256 * KS_STRIDE + 32 * VT_STRIDE + 256 * KS_STRIDE + 256) * 4;
        cudaFuncSetAttribute(attn_tc_kernel,
                             cudaFuncAttributeMaxDynamicSharedMemorySize, smem);
        dim3 grid(4, 256);
        attn_tc_kernel<<<grid, 256, smem>>>(mask, bias, gbias);
    }
    // K3: output projection (tf32) + transpose + add
    {
        const int gemm_smem = (128 * A_STRIDE + 64 * B_STRIDE) * 4;
        cudaFuncSetAttribute(gemm_out_tc_kernel,
                             cudaFuncAttributeMaxDynamicSharedMemorySize, gemm_smem);
        gemm_out_tc_kernel<<<512, 256, gemm_smem>>>(b_o, add_to, out);
    }
}

// round 11
// speedup vs baseline: 3.7391x; 1.2560x over previous
#include <cuda_runtime.h>
#include <cuda_bf16.h>

#define MTOT (256*256)

// Scratch (static device arrays — no allocation in kernel_launch)
__device__ __nv_bfloat16 g_qkvg[(size_t)MTOT * 512];  // [m][q|k|v|g] bf16
__device__ __nv_bfloat16 g_attn[(size_t)MTOT * 128];  // gated attn out bf16
__device__ __nv_bfloat16 g_Wbf[512 * 128];            // W_qkvg quantized, [n=512][k=128]
__device__ float         g_Wot[128 * 128];            // W_o transposed fp32 [k][n]

// ---------------------------------------------------------------------------
// helpers
// ---------------------------------------------------------------------------
__device__ __forceinline__ unsigned f2tf(float x) {
    unsigned u;
    asm("cvt.rna.tf32.f32 %0, %1;" : "=r"(u) : "f"(x));
    return u;
}
__device__ __forceinline__ float f2tff(float x) { return __uint_as_float(f2tf(x)); }
__device__ __forceinline__ float bf_lo(unsigned w) { return __uint_as_float(w << 16); }
__device__ __forceinline__ float bf_hi(unsigned w) { return __uint_as_float(w & 0xffff0000u); }

__device__ __forceinline__ void mma_tf32(float* d, const unsigned* a, const unsigned* b) {
    asm volatile(
        "mma.sync.aligned.m16n8k8.row.col.f32.tf32.tf32.f32 "
        "{%0,%1,%2,%3}, {%4,%5,%6,%7}, {%8,%9}, {%0,%1,%2,%3};"
        : "+f"(d[0]), "+f"(d[1]), "+f"(d[2]), "+f"(d[3])
        : "r"(a[0]), "r"(a[1]), "r"(a[2]), "r"(a[3]),
          "r"(b[0]), "r"(b[1]));
}
__device__ __forceinline__ void mma_bf16(float* d, const unsigned* a, const unsigned* b) {
    asm volatile(
        "mma.sync.aligned.m16n8k16.row.col.f32.bf16.bf16.f32 "
        "{%0,%1,%2,%3}, {%4,%5,%6,%7}, {%8,%9}, {%0,%1,%2,%3};"
        : "+f"(d[0]), "+f"(d[1]), "+f"(d[2]), "+f"(d[3])
        : "r"(a[0]), "r"(a[1]), "r"(a[2]), "r"(a[3]),
          "r"(b[0]), "r"(b[1]));
}

// ---------------------------------------------------------------------------
// K0: quantize W_qkvg to bf16 (already [n][k], no transpose) + fp32 transpose
// of W_o for K3's tf32 path.
// ---------------------------------------------------------------------------
__global__ __launch_bounds__(256) void prep_w_kernel(
    const float* __restrict__ W, const float* __restrict__ Wo)
{
    int idx = blockIdx.x * 256 + threadIdx.x;
    if (idx < 512 * 128) {
        g_Wbf[idx] = __float2bfloat16_rn(W[idx]);
    }
    int idx2 = idx - 512 * 128;
    if (idx2 >= 0 && idx2 < 128 * 128) {
        int k = idx2 >> 7;
        int n = idx2 & 127;
        g_Wot[idx2] = Wo[n * 128 + k];
    }
}

// ---------------------------------------------------------------------------
// K1: QKVG projection, bf16 m16n8k16 MMA.
// Block = 128 m x full N=512 (2 chunks of 256), 512 threads, 16 warps,
// warp tile 32x64.  smem: As[128][68w] bf16x2-words, Bs[512][68w].
// Frag banks: (4g+tig) mod 32 — all distinct, conflict-free.
// ---------------------------------------------------------------------------
#define KW 68   // 32-bit words per row: 64 data (128 bf16) + 4 pad

__global__ __launch_bounds__(512, 1) void gemm_qkvg_bf_kernel(const float* __restrict__ X)
{
    extern __shared__ unsigned shm[];
    unsigned* As = shm;              // [128][KW]
    unsigned* Bs = shm + 128 * KW;   // [512][KW]

    const int tid  = threadIdx.x;
    const int lane = tid & 31;
    const int w    = tid >> 5;
    const int g    = lane >> 2;
    const int t    = lane & 3;
    const int mw   = (w & 3) * 32;
    const int nw   = (w >> 2) * 64;

    const int m0 = blockIdx.x * 128;

    // stage A: X fp32 -> bf16x2 words
    for (int l = tid; l < 4096; l += 512) {
        int r = l >> 5, c4 = (l & 31) << 2;
        float4 v = *(const float4*)&X[(size_t)(m0 + r) * 128 + c4];
        __nv_bfloat162 p0 = __float22bfloat162_rn(make_float2(v.x, v.y));
        __nv_bfloat162 p1 = __float22bfloat162_rn(make_float2(v.z, v.w));
        As[r * KW + (c4 >> 1)]     = *(unsigned*)&p0;
        As[r * KW + (c4 >> 1) + 1] = *(unsigned*)&p1;
    }
    // stage B: g_Wbf rows (128 bf16 = 16 uint4 per row), 512 rows
    for (int l = tid; l < 8192; l += 512) {
        int n = l >> 4, q = l & 15;
        uint4 v = *(const uint4*)&g_Wbf[n * 128 + q * 8];
        *(uint4*)&Bs[n * KW + q * 4] = v;
    }
    __syncthreads();

    #pragma unroll
    for (int chunk = 0; chunk < 2; chunk++) {
        const int nbase = chunk * 256;
        float acc[2][8][4];
        #pragma unroll
        for (int i = 0; i < 2; i++)
            #pragma unroll
            for (int j = 0; j < 8; j++)
                #pragma unroll
                for (int c = 0; c < 4; c++) acc[i][j][c] = 0.f;

        #pragma unroll
        for (int kw = 0; kw < 64; kw += 8) {   // k-step of 16 (8 words)
            unsigned a[2][4], b[8][2];
            #pragma unroll
            for (int fm = 0; fm < 2; fm++) {
                int r = mw + fm * 16 + g;
                a[fm][0] = As[r * KW + kw + t];
                a[fm][1] = As[(r + 8) * KW + kw + t];
                a[fm][2] = As[r * KW + kw + t + 4];
                a[fm][3] = As[(r + 8) * KW + kw + t + 4];
            }
            #pragma unroll
            for (int fn = 0; fn < 8; fn++) {
                int n = nbase + nw + fn * 8 + g;
                b[fn][0] = Bs[n * KW + kw + t];
                b[fn][1] = Bs[n * KW + kw + t + 4];
            }
            #pragma unroll
            for (int fm = 0; fm < 2; fm++)
                #pragma unroll
                for (int fn = 0; fn < 8; fn++)
                    mma_bf16(acc[fm][fn], a[fm], b[fn]);
        }

        // epilogue: bf16 stores
        #pragma unroll
        for (int fm = 0; fm < 2; fm++) {
            int row = m0 + mw + fm * 16 + g;
            #pragma unroll
            for (int fn = 0; fn < 8; fn++) {
                int col = nbase + nw + fn * 8 + 2 * t;
                __nv_bfloat162 lo = __float22bfloat162_rn(make_float2(acc[fm][fn][0], acc[fm][fn][1]));
                __nv_bfloat162 hi = __float22bfloat162_rn(make_float2(acc[fm][fn][2], acc[fm][fn][3]));
                *(__nv_bfloat162*)&g_qkvg[(size_t)row * 512 + col] = lo;
                *(__nv_bfloat162*)&g_qkvg[(size_t)(row + 8) * 512 + col] = hi;
            }
        }
    }
}

// ---------------------------------------------------------------------------
// K2: tensor-core fused attention (tf32 MMA path; bf16 global I/O).
// bf16 -> tf32 is exact, so math is identical to the proven R6 kernel.
// ---------------------------------------------------------------------------
#define KS_STRIDE 36
#define VT_STRIDE 268

__global__ __launch_bounds__(256) void attn_tc_kernel(
    const float* __restrict__ mask, const float* __restrict__ bias,
    const float* __restrict__ gbias)
{
    extern __shared__ float sh[];
    float* Ks   = sh;                           // [256][36]
    float* VsT  = sh + 256 * KS_STRIDE;         // [32][268]
    float* Ps   = VsT + 32 * VT_STRIDE;         // [256][36]
    float* madd = Ps + 256 * KS_STRIDE;         // [256]

    const int h = blockIdx.x;
    const int b = blockIdx.y;
    const int tid  = threadIdx.x;
    const int lane = tid & 31;
    const int w    = tid >> 5;
    const int g    = lane >> 2;
    const int t    = lane & 3;
    const int q0   = w * 32;

    {
        const __nv_bfloat16* base = &g_qkvg[(size_t)(b * 256 + tid) * 512 + h * 32];
        // K rows: 32 bf16 = 2 uint4
        #pragma unroll
        for (int j = 0; j < 2; j++) {
            uint4 u = *(const uint4*)(base + 128 + j * 16);
            float* d = &Ks[tid * KS_STRIDE + j * 16];
            d[0] = bf_lo(u.x); d[1]  = bf_hi(u.x);
            d[2] = bf_lo(u.y); d[3]  = bf_hi(u.y);
            d[4] = bf_lo(u.z); d[5]  = bf_hi(u.z);
            d[6] = bf_lo(u.w); d[7]  = bf_hi(u.w);
            uint4 u2 = *(const uint4*)(base + 128 + j * 16 + 8);
            d[8]  = bf_lo(u2.x); d[9]  = bf_hi(u2.x);
            d[10] = bf_lo(u2.y); d[11] = bf_hi(u2.y);
            d[12] = bf_lo(u2.z); d[13] = bf_hi(u2.z);
            d[14] = bf_lo(u2.w); d[15] = bf_hi(u2.w);
        }
        // V rows -> transposed scatter
        #pragma unroll
        for (int j = 0; j < 4; j++) {
            uint4 u = *(const uint4*)(base + 256 + j * 8);
            VsT[(j * 8 + 0) * VT_STRIDE + tid] = bf_lo(u.x);
            VsT[(j * 8 + 1) * VT_STRIDE + tid] = bf_hi(u.x);
            VsT[(j * 8 + 2) * VT_STRIDE + tid] = bf_lo(u.y);
            VsT[(j * 8 + 3) * VT_STRIDE + tid] = bf_hi(u.y);
            VsT[(j * 8 + 4) * VT_STRIDE + tid] = bf_lo(u.z);
            VsT[(j * 8 + 5) * VT_STRIDE + tid] = bf_hi(u.z);
            VsT[(j * 8 + 6) * VT_STRIDE + tid] = bf_lo(u.w);
            VsT[(j * 8 + 7) * VT_STRIDE + tid] = bf_hi(u.w);
        }
        // Q rows (scaled, tf32)
        #pragma unroll
        for (int j = 0; j < 4; j++) {
            uint4 u = *(const uint4*)(base + j * 8);
            float* d = &Ps[tid * KS_STRIDE + j * 8];
            const float s = 0.17677669529663687f;
            d[0] = f2tff(bf_lo(u.x) * s); d[1] = f2tff(bf_hi(u.x) * s);
            d[2] = f2tff(bf_lo(u.y) * s); d[3] = f2tff(bf_hi(u.y) * s);
            d[4] = f2tff(bf_lo(u.z) * s); d[5] = f2tff(bf_hi(u.z) * s);
            d[6] = f2tff(bf_lo(u.w) * s); d[7] = f2tff(bf_hi(u.w) * s);
        }
        madd[tid] = (mask[(size_t)b * 256 + tid] - 1.0f) * 1e9f;
    }
    __syncthreads();

    unsigned Qa[2][4][4];
    #pragma unroll
    for (int mf = 0; mf < 2; mf++) {
        int r = q0 + 16 * mf + g;
        #pragma unroll
        for (int ks = 0; ks < 4; ks++) {
            Qa[mf][ks][0] = __float_as_uint(Ps[r * KS_STRIDE + 8 * ks + t]);
            Qa[mf][ks][1] = __float_as_uint(Ps[(r + 8) * KS_STRIDE + 8 * ks + t]);
            Qa[mf][ks][2] = __float_as_uint(Ps[r * KS_STRIDE + 8 * ks + t + 4]);
            Qa[mf][ks][3] = __float_as_uint(Ps[(r + 8) * KS_STRIDE + 8 * ks + t + 4]);
        }
    }
    __syncwarp();

    float Oacc[2][4][4];
    #pragma unroll
    for (int i = 0; i < 2; i++)
        #pragma unroll
        for (int j = 0; j < 4; j++)
            #pragma unroll
            for (int c = 0; c < 4; c++) Oacc[i][j][c] = 0.f;
    float lsum[4] = {0.f, 0.f, 0.f, 0.f};

    float* Pw = Ps + q0 * KS_STRIDE;
    const float* biasw = &bias[((size_t)h * 256 + q0) * 256];

    for (int k0 = 0; k0 < 256; k0 += 32) {
        float Sacc[2][4][4];
        #pragma unroll
        for (int i = 0; i < 2; i++)
            #pragma unroll
            for (int j = 0; j < 4; j++)
                #pragma unroll
                for (int c = 0; c < 4; c++) Sacc[i][j][c] = 0.f;

        #pragma unroll
        for (int ks = 0; ks < 4; ks++) {
            unsigned bf[4][2];
            #pragma unroll
            for (int nf = 0; nf < 4; nf++) {
                int krow = k0 + 8 * nf + g;
                bf[nf][0] = __float_as_uint(Ks[krow * KS_STRIDE + 8 * ks + t]);
                bf[nf][1] = __float_as_uint(Ks[krow * KS_STRIDE + 8 * ks + t + 4]);
            }
            #pragma unroll
            for (int mf = 0; mf < 2; mf++)
                #pragma unroll
                for (int nf = 0; nf < 4; nf++)
                    mma_tf32(Sacc[mf][nf], Qa[mf][ks], bf[nf]);
        }

        #pragma unroll
        for (int nf = 0; nf < 4; nf++) {
            int col = k0 + 8 * nf + 2 * t;
            float2 md = *(const float2*)&madd[col];
            #pragma unroll
            for (int mf = 0; mf < 2; mf++) {
                int rloc = 16 * mf + g;
                float2 bz0 = *(const float2*)&biasw[(size_t)rloc * 256 + col];
                float2 bz1 = *(const float2*)&biasw[(size_t)(rloc + 8) * 256 + col];
                float p00 = __expf(Sacc[mf][nf][0] + md.x + bz0.x);
                float p01 = __expf(Sacc[mf][nf][1] + md.y + bz0.y);
                float p10 = __expf(Sacc[mf][nf][2] + md.x + bz1.x);
                float p11 = __expf(Sacc[mf][nf][3] + md.y + bz1.y);
                lsum[mf * 2 + 0] += p00 + p01;
                lsum[mf * 2 + 1] += p10 + p11;
                float2 s0 = { f2tff(p00), f2tff(p01) };
                float2 s1 = { f2tff(p10), f2tff(p11) };
                *(float2*)&Pw[rloc * KS_STRIDE + 8 * nf + 2 * t] = s0;
                *(float2*)&Pw[(rloc + 8) * KS_STRIDE + 8 * nf + 2 * t] = s1;
            }
        }
        __syncwarp();

        #pragma unroll
        for (int ks = 0; ks < 4; ks++) {
            unsigned af[2][4], bf[4][2];
            #pragma unroll
            for (int mf = 0; mf < 2; mf++) {
                int rloc = 16 * mf + g;
                af[mf][0] = __float_as_uint(Pw[rloc * KS_STRIDE + 8 * ks + t]);
                af[mf][1] = __float_as_uint(Pw[(rloc + 8) * KS_STRIDE + 8 * ks + t]);
                af[mf][2] = __float_as_uint(Pw[rloc * KS_STRIDE + 8 * ks + t + 4]);
                af[mf][3] = __float_as_uint(Pw[(rloc + 8) * KS_STRIDE + 8 * ks + t + 4]);
            }
            #pragma unroll
            for (int nf = 0; nf < 4; nf++) {
                bf[nf][0] = __float_as_uint(VsT[(8 * nf + g) * VT_STRIDE + k0 + 8 * ks + t]);
                bf[nf][1] = __float_as_uint(VsT[(8 * nf + g) * VT_STRIDE + k0 + 8 * ks + t + 4]);
            }
            #pragma unroll
            for (int mf = 0; mf < 2; mf++)
                #pragma unroll
                for (int nf = 0; nf < 4; nf++)
                    mma_tf32(Oacc[mf][nf], af[mf], bf[nf]);
        }
        __syncwarp();
    }

    float inv[4];
    #pragma unroll
    for (int j = 0; j < 4; j++) {
        float l = lsum[j];
        l += __shfl_xor_sync(0xffffffff, l, 1);
        l += __shfl_xor_sync(0xffffffff, l, 2);
        inv[j] = 1.0f / l;
    }

    #pragma unroll
    for (int mf = 0; mf < 2; mf++) {
        #pragma unroll
        for (int half = 0; half < 2; half++) {
            int r = q0 + 16 * mf + g + half * 8;
            float iv = inv[mf * 2 + half];
            const __nv_bfloat16* grow = &g_qkvg[(size_t)(b * 256 + r) * 512 + 384 + h * 32];
            __nv_bfloat16* orow = &g_attn[(size_t)(b * 256 + r) * 128 + h * 32];
            #pragma unroll
            for (int nf = 0; nf < 4; nf++) {
                int c = 8 * nf + 2 * t;
                unsigned gw = *(const unsigned*)(grow + c);
                float2 gb = *(const float2*)&gbias[h * 32 + c];
                float g0 = bf_lo(gw) + gb.x;
                float g1 = bf_hi(gw) + gb.y;
                float ox = Oacc[mf][nf][half * 2 + 0] * iv;
                float oy = Oacc[mf][nf][half * 2 + 1] * iv;
                float rx = ox * (1.0f / (1.0f + __expf(-g0)));
                float ry = oy * (1.0f / (1.0f + __expf(-g1)));
                *(__nv_bfloat162*)(orow + c) = __float22bfloat162_rn(make_float2(rx, ry));
            }
        }
    }
}

// ---------------------------------------------------------------------------
// K3: output projection (tf32 MMA) + transpose + add.  A read from bf16 g_attn
// (exact cvt to tf32); otherwise the proven R5-R10 kernel.
// ---------------------------------------------------------------------------
#define A_STRIDE 68
#define B_STRIDE 136

__global__ __launch_bounds__(256) void gemm_out_tc_kernel(
    const float* __restrict__ bo, const float* __restrict__ add,
    float* __restrict__ out)
{
    extern __shared__ unsigned shm[];
    unsigned* As = shm;                  // [128][A_STRIDE]
    unsigned* Ws = shm + 128 * A_STRIDE; // [64][B_STRIDE]

    const int tid  = threadIdx.x;
    const int lane = tid & 31;
    const int w    = tid >> 5;
    const int g    = lane >> 2;
    const int t    = lane & 3;
    const int mw   = (w & 3) * 32;
    const int nw   = (w >> 2) * 64;

    const int m0 = blockIdx.x * 128;

    float acc[2][8][4];
    #pragma unroll
    for (int i = 0; i < 2; i++)
        #pragma unroll
        for (int j = 0; j < 8; j++)
            #pragma unroll
            for (int c = 0; c < 4; c++) acc[i][j][c] = 0.f;

    for (int kc = 0; kc < 128; kc += 64) {
        for (int l = tid; l < 2048; l += 256) {
            int r = l >> 4, c4 = (l & 15) << 2;
            uint2 u = *(const uint2*)&g_attn[(size_t)(m0 + r) * 128 + kc + c4];
            unsigned* d = &As[r * A_STRIDE + c4];
            d[0] = u.x << 16; d[1] = u.x & 0xffff0000u;
            d[2] = u.y << 16; d[3] = u.y & 0xffff0000u;
        }
        for (int l = tid; l < 2048; l += 256) {
            int r = l >> 5, c4 = (l & 31) << 2;
            float4 v = *(const float4*)&g_Wot[(size_t)(kc + r) * 128 + c4];
            unsigned* d = &Ws[r * B_STRIDE + c4];
            d[0] = f2tf(v.x); d[1] = f2tf(v.y); d[2] = f2tf(v.z); d[3] = f2tf(v.w);
        }
        __syncthreads();

        #pragma unroll
        for (int ks = 0; ks < 64; ks += 8) {
            unsigned a[2][4], b[8][2];
            #pragma unroll
            for (int fm = 0; fm < 2; fm++) {
                int r = mw + fm * 16 + g;
                a[fm][0] = As[r * A_STRIDE + ks + t];
                a[fm][1] = As[(r + 8) * A_STRIDE + ks + t];
                a[fm][2] = As[r * A_STRIDE + ks + t + 4];
                a[fm][3] = As[(r + 8) * A_STRIDE + ks + t + 4];
            }
            #pragma unroll
            for (int fn = 0; fn < 8; fn++) {
                int n = nw + fn * 8 + g;
                b[fn][0] = Ws[(ks + t) * B_STRIDE + n];
                b[fn][1] = Ws[(ks + t + 4) * B_STRIDE + n];
            }
            #pragma unroll
            for (int fm = 0; fm < 2; fm++)
                #pragma unroll
                for (int fn = 0; fn < 8; fn++)
                    mma_tf32(acc[fm][fn], a[fm], b[fn]);
        }
        __syncthreads();
    }

    #pragma unroll
    for (int fm = 0; fm < 2; fm++) {
        int m_lo = m0 + mw + fm * 16 + g;
        #pragma unroll
        for (int fn = 0; fn < 8; fn++) {
            int n = nw + fn * 8 + 2 * t;
            float bx = bo[n], by = bo[n + 1];
            {
                int m = m_lo;
                int bb = m >> 8, ss = m & 255;
                size_t base = ((size_t)ss * 256 + bb) * 128 + n;
                float2 av = *(const float2*)&add[base];
                float2 r = { acc[fm][fn][0] + bx + av.x, acc[fm][fn][1] + by + av.y };
                *(float2*)&out[base] = r;
            }
            {
                int m = m_lo + 8;
                int bb = m >> 8, ss = m & 255;
                size_t base = ((size_t)ss * 256 + bb) * 128 + n;
                float2 av = *(const float2*)&add[base];
                float2 r = { acc[fm][fn][2] + bx + av.x, acc[fm][fn][3] + by + av.y };
                *(float2*)&out[base] = r;
            }
        }
    }
}

// ---------------------------------------------------------------------------
extern "C" void kernel_launch(void* const* d_in, const int* in_sizes, int n_in,
                              void* d_out, int out_size)
{
    const float* input_qkv = (const float*)d_in[0];
    const float* mask      = (const float*)d_in[1];
    const float* bias      = (const float*)d_in[2];
    const float* add_to    = (const float*)d_in[3];
    const float* W_qkvg    = (const float*)d_in[4];
    const float* gbias     = (const float*)d_in[5];
    const float* W_o       = (const float*)d_in[6];
    const float* b_o       = (const float*)d_in[7];
    float* out = (float*)d_out;

    // K0: weight prep (quantize + transpose)
    prep_w_kernel<<<(512*128 + 128*128 + 255) / 256, 256>>>(W_qkvg, W_o);

    // K1: QKVG projection (bf16 m16n8k16, A+B fully resident)
    {
        const int smem = (128 * KW + 512 * KW) * 4;  // 174080 B
        cudaFuncSetAttribute(gemm_qkvg_bf_kernel,
                             cudaFuncAttributeMaxDynamicSharedMemorySize, smem);
        gemm_qkvg_bf_kernel<<<512, 512, smem>>>(input_qkv);
    }
    // K2: tensor-core fused attention (bf16 I/O, tf32 math)
    {
        const int smem = (256 * KS_STRIDE + 32 * VT_STRIDE + 256 * KS_STRIDE + 256) * 4;
        cudaFuncSetAttribute(attn_tc_kernel,
                             cudaFuncAttributeMaxDynamicSharedMemorySize, smem);
        dim3 grid(4, 256);
        attn_tc_kernel<<<grid, 256, smem>>>(mask, bias, gbias);
    }
    // K3: output projection (tf32) + transpose + add
    {
        const int gemm_smem = (128 * A_STRIDE + 64 * B_STRIDE) * 4;
        cudaFuncSetAttribute(gemm_out_tc_kernel,
                             cudaFuncAttributeMaxDynamicSharedMemorySize, gemm_smem);
        gemm_out_tc_kernel<<<512, 256, gemm_smem>>>(b_o, add_to, out);
    }
}